// round 1
// baseline (speedup 1.0000x reference)
#include <cuda_runtime.h>
#include <cstdint>
#include <cstddef>

#define NTOK 8192
#define CDIM 512
#define HHEADS 8

// Scratch (allocation-free rule: __device__ globals)
__device__ float g_Q[NTOK * CDIM];                 // 16.8 MB
__device__ float g_Kp[NTOK * CDIM];                // 16.8 MB
__device__ float g_S[(size_t)NTOK * NTOK];         // 268 MB
__device__ float g_Y[NTOK * CDIM];                 // 16.8 MB

// ---------------------------------------------------------------------------
// SGEMM NN: C[M,N] = A[M,K] @ B[K,N] (+ bias[N] if non-null)
// 128x128 tile, BK=8, 256 threads, 8x8 per-thread micro-tile.
// Requires M%128==0, N%128==0, K%8==0 (all shapes here satisfy this).
// ---------------------------------------------------------------------------
__global__ __launch_bounds__(256, 1)
void sgemm_nn(const float* __restrict__ A, const float* __restrict__ B,
              const float* __restrict__ bias, float* __restrict__ C,
              int M, int Nn, int K)
{
    __shared__ float As[8][128];
    __shared__ float Bs[8][128];
    const int tid  = threadIdx.x;
    const int row0 = blockIdx.y * 128;
    const int col0 = blockIdx.x * 128;

    const int ar = tid >> 1;            // A tile: 128 rows x 8 k
    const int ac = (tid & 1) << 2;
    const int br = tid >> 5;            // B tile: 8 k x 128 cols
    const int bc = (tid & 31) << 2;
    const int tr = (tid >> 4) << 3;
    const int tc = (tid & 15) << 3;

    const float* Ap = A + (size_t)(row0 + ar) * K + ac;
    const float* Bp = B + (size_t)br * Nn + (col0 + bc);

    float acc[8][8];
#pragma unroll
    for (int i = 0; i < 8; ++i)
#pragma unroll
        for (int j = 0; j < 8; ++j) acc[i][j] = 0.f;

    for (int k0 = 0; k0 < K; k0 += 8) {
        float4 a4 = *(const float4*)(Ap + k0);
        float4 b4 = *(const float4*)(Bp + (size_t)k0 * Nn);
        __syncthreads();
        As[ac + 0][ar] = a4.x; As[ac + 1][ar] = a4.y;
        As[ac + 2][ar] = a4.z; As[ac + 3][ar] = a4.w;
        *(float4*)&Bs[br][bc] = b4;
        __syncthreads();
#pragma unroll
        for (int kk = 0; kk < 8; ++kk) {
            float ra[8], rb[8];
#pragma unroll
            for (int i = 0; i < 8; ++i) ra[i] = As[kk][tr + i];
#pragma unroll
            for (int j = 0; j < 8; ++j) rb[j] = Bs[kk][tc + j];
#pragma unroll
            for (int i = 0; i < 8; ++i)
#pragma unroll
                for (int j = 0; j < 8; ++j)
                    acc[i][j] = fmaf(ra[i], rb[j], acc[i][j]);
        }
    }

#pragma unroll
    for (int i = 0; i < 8; ++i) {
        float* Cp = C + (size_t)(row0 + tr + i) * Nn + (col0 + tc);
#pragma unroll
        for (int j = 0; j < 8; ++j) {
            float v = acc[i][j];
            if (bias) v += bias[col0 + tc + j];
            Cp[j] = v;
        }
    }
}

// ---------------------------------------------------------------------------
// SGEMM NT: C[M,N] = A[M,K] @ B[N,K]^T      (sim = Q @ K^T)
// ---------------------------------------------------------------------------
__global__ __launch_bounds__(256, 1)
void sgemm_nt(const float* __restrict__ A, const float* __restrict__ B,
              float* __restrict__ C, int M, int Nn, int K)
{
    __shared__ float As[8][128];
    __shared__ float Bs[8][128];
    const int tid  = threadIdx.x;
    const int row0 = blockIdx.y * 128;
    const int col0 = blockIdx.x * 128;

    const int ar = tid >> 1;
    const int ac = (tid & 1) << 2;
    const int tr = (tid >> 4) << 3;
    const int tc = (tid & 15) << 3;

    const float* Ap = A + (size_t)(row0 + ar) * K + ac;
    const float* Bp = B + (size_t)(col0 + ar) * K + ac;  // B row = n, contiguous k

    float acc[8][8];
#pragma unroll
    for (int i = 0; i < 8; ++i)
#pragma unroll
        for (int j = 0; j < 8; ++j) acc[i][j] = 0.f;

    for (int k0 = 0; k0 < K; k0 += 8) {
        float4 a4 = *(const float4*)(Ap + k0);
        float4 b4 = *(const float4*)(Bp + k0);
        __syncthreads();
        As[ac + 0][ar] = a4.x; As[ac + 1][ar] = a4.y;
        As[ac + 2][ar] = a4.z; As[ac + 3][ar] = a4.w;
        Bs[ac + 0][ar] = b4.x; Bs[ac + 1][ar] = b4.y;
        Bs[ac + 2][ar] = b4.z; Bs[ac + 3][ar] = b4.w;
        __syncthreads();
#pragma unroll
        for (int kk = 0; kk < 8; ++kk) {
            float ra[8], rb[8];
#pragma unroll
            for (int i = 0; i < 8; ++i) ra[i] = As[kk][tr + i];
#pragma unroll
            for (int j = 0; j < 8; ++j) rb[j] = Bs[kk][tc + j];
#pragma unroll
            for (int i = 0; i < 8; ++i)
#pragma unroll
                for (int j = 0; j < 8; ++j)
                    acc[i][j] = fmaf(ra[i], rb[j], acc[i][j]);
        }
    }

#pragma unroll
    for (int i = 0; i < 8; ++i) {
        float* Cp = C + (size_t)(row0 + tr + i) * Nn + (col0 + tc);
#pragma unroll
        for (int j = 0; j < 8; ++j) Cp[j] = acc[i][j];
    }
}

// ---------------------------------------------------------------------------
// Row softmax in place over S[NTOK, NTOK]. One block (256 thr) per row.
// ---------------------------------------------------------------------------
__device__ __forceinline__ float warp_max(float v) {
#pragma unroll
    for (int o = 16; o > 0; o >>= 1) v = fmaxf(v, __shfl_xor_sync(0xffffffffu, v, o));
    return v;
}
__device__ __forceinline__ float warp_sum(float v) {
#pragma unroll
    for (int o = 16; o > 0; o >>= 1) v += __shfl_xor_sync(0xffffffffu, v, o);
    return v;
}

__global__ __launch_bounds__(256, 4)
void softmax_rows(float* __restrict__ S)
{
    float* r = S + (size_t)blockIdx.x * NTOK;
    const int tid = threadIdx.x;
    __shared__ float red[8];

    float v[32];
    float m = -3.4e38f;
#pragma unroll
    for (int i = 0; i < 32; ++i) {
        v[i] = r[i * 256 + tid];
        m = fmaxf(m, v[i]);
    }
    m = warp_max(m);
    if ((tid & 31) == 0) red[tid >> 5] = m;
    __syncthreads();
    {
        float t = red[tid & 7];
        t = fmaxf(t, __shfl_xor_sync(0xffffffffu, t, 1));
        t = fmaxf(t, __shfl_xor_sync(0xffffffffu, t, 2));
        t = fmaxf(t, __shfl_xor_sync(0xffffffffu, t, 4));
        m = t;
    }

    float s = 0.f;
#pragma unroll
    for (int i = 0; i < 32; ++i) {
        v[i] = __expf(v[i] - m);
        s += v[i];
    }
    s = warp_sum(s);
    __syncthreads();
    if ((tid & 31) == 0) red[tid >> 5] = s;
    __syncthreads();
    {
        float t = red[tid & 7];
        t += __shfl_xor_sync(0xffffffffu, t, 1);
        t += __shfl_xor_sync(0xffffffffu, t, 2);
        t += __shfl_xor_sync(0xffffffffu, t, 4);
        s = t;
    }
    const float inv = 1.f / s;
#pragma unroll
    for (int i = 0; i < 32; ++i) r[i * 256 + tid] = v[i] * inv;
}

// ---------------------------------------------------------------------------
// Heads kernel: out[n,d] = (1/8) * sum_h relu( (Y @ W_k[h])[n,d] + b_k[h,d] )
// Same tiling as sgemm_nn; loops h inside the block (Y tile re-read per head,
// only 8*16.8MB total traffic). No atomics -> deterministic output.
// ---------------------------------------------------------------------------
__global__ __launch_bounds__(256, 1)
void heads_kernel(const float* __restrict__ Y, const float* __restrict__ Wk,
                  const float* __restrict__ bk, float* __restrict__ out)
{
    const int M = NTOK, Nn = CDIM, K = CDIM;
    __shared__ float As[8][128];
    __shared__ float Bs[8][128];
    const int tid  = threadIdx.x;
    const int row0 = blockIdx.y * 128;
    const int col0 = blockIdx.x * 128;

    const int ar = tid >> 1;
    const int ac = (tid & 1) << 2;
    const int br = tid >> 5;
    const int bc = (tid & 31) << 2;
    const int tr = (tid >> 4) << 3;
    const int tc = (tid & 15) << 3;

    const float* Ap = Y + (size_t)(row0 + ar) * K + ac;

    float oacc[8][8];
#pragma unroll
    for (int i = 0; i < 8; ++i)
#pragma unroll
        for (int j = 0; j < 8; ++j) oacc[i][j] = 0.f;

    for (int h = 0; h < HHEADS; ++h) {
        const float* Bp = Wk + (size_t)h * CDIM * CDIM + (size_t)br * Nn + (col0 + bc);
        float acc[8][8];
#pragma unroll
        for (int i = 0; i < 8; ++i)
#pragma unroll
            for (int j = 0; j < 8; ++j) acc[i][j] = 0.f;

        for (int k0 = 0; k0 < K; k0 += 8) {
            float4 a4 = *(const float4*)(Ap + k0);
            float4 b4 = *(const float4*)(Bp + (size_t)k0 * Nn);
            __syncthreads();
            As[ac + 0][ar] = a4.x; As[ac + 1][ar] = a4.y;
            As[ac + 2][ar] = a4.z; As[ac + 3][ar] = a4.w;
            *(float4*)&Bs[br][bc] = b4;
            __syncthreads();
#pragma unroll
            for (int kk = 0; kk < 8; ++kk) {
                float ra[8], rb[8];
#pragma unroll
                for (int i = 0; i < 8; ++i) ra[i] = As[kk][tr + i];
#pragma unroll
                for (int j = 0; j < 8; ++j) rb[j] = Bs[kk][tc + j];
#pragma unroll
                for (int i = 0; i < 8; ++i)
#pragma unroll
                    for (int j = 0; j < 8; ++j)
                        acc[i][j] = fmaf(ra[i], rb[j], acc[i][j]);
            }
        }
#pragma unroll
        for (int i = 0; i < 8; ++i)
#pragma unroll
            for (int j = 0; j < 8; ++j) {
                float v = acc[i][j] + bk[h * CDIM + col0 + tc + j];
                oacc[i][j] += fmaxf(v, 0.f);
            }
    }

#pragma unroll
    for (int i = 0; i < 8; ++i) {
        float* Op = out + (size_t)(row0 + tr + i) * Nn + (col0 + tc);
#pragma unroll
        for (int j = 0; j < 8; ++j) Op[j] = oacc[i][j] * 0.125f;
    }
}

// ---------------------------------------------------------------------------
extern "C" void kernel_launch(void* const* d_in, const int* in_sizes, int n_in,
                              void* d_out, int out_size)
{
    (void)in_sizes; (void)n_in; (void)out_size;
    const float* x  = (const float*)d_in[0];
    const float* Wt = (const float*)d_in[1];
    const float* bt = (const float*)d_in[2];
    const float* Wp = (const float*)d_in[3];
    const float* bp = (const float*)d_in[4];
    const float* Wk = (const float*)d_in[5];
    const float* bk = (const float*)d_in[6];
    float* out = (float*)d_out;

    float *Q, *Kp, *S, *Y;
    cudaGetSymbolAddress((void**)&Q,  g_Q);
    cudaGetSymbolAddress((void**)&Kp, g_Kp);
    cudaGetSymbolAddress((void**)&S,  g_S);
    cudaGetSymbolAddress((void**)&Y,  g_Y);

    const dim3 blk(256);

    // 1) Q = x @ W_theta + b_theta ; K = x @ W_phi + b_phi
    sgemm_nn<<<dim3(CDIM / 128, NTOK / 128), blk>>>(x, Wt, bt, Q, NTOK, CDIM, CDIM);
    sgemm_nn<<<dim3(CDIM / 128, NTOK / 128), blk>>>(x, Wp, bp, Kp, NTOK, CDIM, CDIM);

    // 2) S = Q @ K^T
    sgemm_nt<<<dim3(NTOK / 128, NTOK / 128), blk>>>(Q, Kp, S, NTOK, NTOK, CDIM);

    // 3) row softmax in place
    softmax_rows<<<NTOK, blk>>>(S);

    // 4) Y = adj @ x   (factorization: adj @ (x@Wk[h]+b) == (adj@x)@Wk[h]+b)
    sgemm_nn<<<dim3(CDIM / 128, NTOK / 128), blk>>>(S, x, nullptr, Y, NTOK, CDIM, NTOK);

    // 5) out = mean_h relu(Y @ Wk[h] + bk[h])
    heads_kernel<<<dim3(CDIM / 128, NTOK / 128), blk>>>(Y, Wk, bk, out);
}

// round 2
// speedup vs baseline: 1.0027x; 1.0027x over previous
#include <cuda_runtime.h>
#include <cstdint>
#include <cstddef>

#define NTOK 8192
#define CDIM 512
#define HHEADS 8

// Scratch (allocation-free rule: __device__ globals)
__device__ float g_Q[NTOK * CDIM];                 // 16.8 MB
__device__ float g_Kp[NTOK * CDIM];                // 16.8 MB
__device__ float g_S[(size_t)NTOK * NTOK];         // 268 MB
__device__ float g_Y[NTOK * CDIM];                 // 16.8 MB

// ---------------------------------------------------------------------------
// SGEMM NN: C[M,N] = A[M,K] @ B[K,N] (+ bias[N] if non-null)
// 128x128 tile, BK=8, 256 threads, 8x8 per-thread micro-tile.
// Requires M%128==0, N%128==0, K%8==0 (all shapes here satisfy this).
// ---------------------------------------------------------------------------
__global__ __launch_bounds__(256, 1)
void sgemm_nn(const float* __restrict__ A, const float* __restrict__ B,
              const float* __restrict__ bias, float* __restrict__ C,
              int M, int Nn, int K)
{
    __shared__ float As[8][128];
    __shared__ float Bs[8][128];
    const int tid  = threadIdx.x;
    const int row0 = blockIdx.y * 128;
    const int col0 = blockIdx.x * 128;

    const int ar = tid >> 1;            // A tile: 128 rows x 8 k
    const int ac = (tid & 1) << 2;
    const int br = tid >> 5;            // B tile: 8 k x 128 cols
    const int bc = (tid & 31) << 2;
    const int tr = (tid >> 4) << 3;
    const int tc = (tid & 15) << 3;

    const float* Ap = A + (size_t)(row0 + ar) * K + ac;
    const float* Bp = B + (size_t)br * Nn + (col0 + bc);

    float acc[8][8];
#pragma unroll
    for (int i = 0; i < 8; ++i)
#pragma unroll
        for (int j = 0; j < 8; ++j) acc[i][j] = 0.f;

    for (int k0 = 0; k0 < K; k0 += 8) {
        float4 a4 = *(const float4*)(Ap + k0);
        float4 b4 = *(const float4*)(Bp + (size_t)k0 * Nn);
        __syncthreads();
        As[ac + 0][ar] = a4.x; As[ac + 1][ar] = a4.y;
        As[ac + 2][ar] = a4.z; As[ac + 3][ar] = a4.w;
        *(float4*)&Bs[br][bc] = b4;
        __syncthreads();
#pragma unroll
        for (int kk = 0; kk < 8; ++kk) {
            float ra[8], rb[8];
#pragma unroll
            for (int i = 0; i < 8; ++i) ra[i] = As[kk][tr + i];
#pragma unroll
            for (int j = 0; j < 8; ++j) rb[j] = Bs[kk][tc + j];
#pragma unroll
            for (int i = 0; i < 8; ++i)
#pragma unroll
                for (int j = 0; j < 8; ++j)
                    acc[i][j] = fmaf(ra[i], rb[j], acc[i][j]);
        }
    }

#pragma unroll
    for (int i = 0; i < 8; ++i) {
        float* Cp = C + (size_t)(row0 + tr + i) * Nn + (col0 + tc);
#pragma unroll
        for (int j = 0; j < 8; ++j) {
            float v = acc[i][j];
            if (bias) v += bias[col0 + tc + j];
            Cp[j] = v;
        }
    }
}

// ---------------------------------------------------------------------------
// SGEMM NT: C[M,N] = A[M,K] @ B[N,K]^T      (sim = Q @ K^T)
// ---------------------------------------------------------------------------
__global__ __launch_bounds__(256, 1)
void sgemm_nt(const float* __restrict__ A, const float* __restrict__ B,
              float* __restrict__ C, int M, int Nn, int K)
{
    __shared__ float As[8][128];
    __shared__ float Bs[8][128];
    const int tid  = threadIdx.x;
    const int row0 = blockIdx.y * 128;
    const int col0 = blockIdx.x * 128;

    const int ar = tid >> 1;
    const int ac = (tid & 1) << 2;
    const int tr = (tid >> 4) << 3;
    const int tc = (tid & 15) << 3;

    const float* Ap = A + (size_t)(row0 + ar) * K + ac;
    const float* Bp = B + (size_t)(col0 + ar) * K + ac;  // B row = n, contiguous k

    float acc[8][8];
#pragma unroll
    for (int i = 0; i < 8; ++i)
#pragma unroll
        for (int j = 0; j < 8; ++j) acc[i][j] = 0.f;

    for (int k0 = 0; k0 < K; k0 += 8) {
        float4 a4 = *(const float4*)(Ap + k0);
        float4 b4 = *(const float4*)(Bp + k0);
        __syncthreads();
        As[ac + 0][ar] = a4.x; As[ac + 1][ar] = a4.y;
        As[ac + 2][ar] = a4.z; As[ac + 3][ar] = a4.w;
        Bs[ac + 0][ar] = b4.x; Bs[ac + 1][ar] = b4.y;
        Bs[ac + 2][ar] = b4.z; Bs[ac + 3][ar] = b4.w;
        __syncthreads();
#pragma unroll
        for (int kk = 0; kk < 8; ++kk) {
            float ra[8], rb[8];
#pragma unroll
            for (int i = 0; i < 8; ++i) ra[i] = As[kk][tr + i];
#pragma unroll
            for (int j = 0; j < 8; ++j) rb[j] = Bs[kk][tc + j];
#pragma unroll
            for (int i = 0; i < 8; ++i)
#pragma unroll
                for (int j = 0; j < 8; ++j)
                    acc[i][j] = fmaf(ra[i], rb[j], acc[i][j]);
        }
    }

#pragma unroll
    for (int i = 0; i < 8; ++i) {
        float* Cp = C + (size_t)(row0 + tr + i) * Nn + (col0 + tc);
#pragma unroll
        for (int j = 0; j < 8; ++j) Cp[j] = acc[i][j];
    }
}

// ---------------------------------------------------------------------------
// Row softmax in place over S[NTOK, NTOK]. One block (256 thr) per row.
// ---------------------------------------------------------------------------
__device__ __forceinline__ float warp_max(float v) {
#pragma unroll
    for (int o = 16; o > 0; o >>= 1) v = fmaxf(v, __shfl_xor_sync(0xffffffffu, v, o));
    return v;
}
__device__ __forceinline__ float warp_sum(float v) {
#pragma unroll
    for (int o = 16; o > 0; o >>= 1) v += __shfl_xor_sync(0xffffffffu, v, o);
    return v;
}

__global__ __launch_bounds__(256, 4)
void softmax_rows(float* __restrict__ S)
{
    float* r = S + (size_t)blockIdx.x * NTOK;
    const int tid = threadIdx.x;
    __shared__ float red[8];

    float v[32];
    float m = -3.4e38f;
#pragma unroll
    for (int i = 0; i < 32; ++i) {
        v[i] = r[i * 256 + tid];
        m = fmaxf(m, v[i]);
    }
    m = warp_max(m);
    if ((tid & 31) == 0) red[tid >> 5] = m;
    __syncthreads();
    {
        float t = red[tid & 7];
        t = fmaxf(t, __shfl_xor_sync(0xffffffffu, t, 1));
        t = fmaxf(t, __shfl_xor_sync(0xffffffffu, t, 2));
        t = fmaxf(t, __shfl_xor_sync(0xffffffffu, t, 4));
        m = t;
    }

    float s = 0.f;
#pragma unroll
    for (int i = 0; i < 32; ++i) {
        v[i] = __expf(v[i] - m);
        s += v[i];
    }
    s = warp_sum(s);
    __syncthreads();
    if ((tid & 31) == 0) red[tid >> 5] = s;
    __syncthreads();
    {
        float t = red[tid & 7];
        t += __shfl_xor_sync(0xffffffffu, t, 1);
        t += __shfl_xor_sync(0xffffffffu, t, 2);
        t += __shfl_xor_sync(0xffffffffu, t, 4);
        s = t;
    }
    const float inv = 1.f / s;
#pragma unroll
    for (int i = 0; i < 32; ++i) r[i * 256 + tid] = v[i] * inv;
}

// ---------------------------------------------------------------------------
// Heads kernel: out[n,d] = (1/8) * sum_h relu( (Y @ W_k[h])[n,d] + b_k[h,d] )
// Same tiling as sgemm_nn; loops h inside the block (Y tile re-read per head,
// only 8*16.8MB total traffic). No atomics -> deterministic output.
// ---------------------------------------------------------------------------
__global__ __launch_bounds__(256, 1)
void heads_kernel(const float* __restrict__ Y, const float* __restrict__ Wk,
                  const float* __restrict__ bk, float* __restrict__ out)
{
    const int M = NTOK, Nn = CDIM, K = CDIM;
    __shared__ float As[8][128];
    __shared__ float Bs[8][128];
    const int tid  = threadIdx.x;
    const int row0 = blockIdx.y * 128;
    const int col0 = blockIdx.x * 128;

    const int ar = tid >> 1;
    const int ac = (tid & 1) << 2;
    const int br = tid >> 5;
    const int bc = (tid & 31) << 2;
    const int tr = (tid >> 4) << 3;
    const int tc = (tid & 15) << 3;

    const float* Ap = Y + (size_t)(row0 + ar) * K + ac;

    float oacc[8][8];
#pragma unroll
    for (int i = 0; i < 8; ++i)
#pragma unroll
        for (int j = 0; j < 8; ++j) oacc[i][j] = 0.f;

    for (int h = 0; h < HHEADS; ++h) {
        const float* Bp = Wk + (size_t)h * CDIM * CDIM + (size_t)br * Nn + (col0 + bc);
        float acc[8][8];
#pragma unroll
        for (int i = 0; i < 8; ++i)
#pragma unroll
            for (int j = 0; j < 8; ++j) acc[i][j] = 0.f;

        for (int k0 = 0; k0 < K; k0 += 8) {
            float4 a4 = *(const float4*)(Ap + k0);
            float4 b4 = *(const float4*)(Bp + (size_t)k0 * Nn);
            __syncthreads();
            As[ac + 0][ar] = a4.x; As[ac + 1][ar] = a4.y;
            As[ac + 2][ar] = a4.z; As[ac + 3][ar] = a4.w;
            *(float4*)&Bs[br][bc] = b4;
            __syncthreads();
#pragma unroll
            for (int kk = 0; kk < 8; ++kk) {
                float ra[8], rb[8];
#pragma unroll
                for (int i = 0; i < 8; ++i) ra[i] = As[kk][tr + i];
#pragma unroll
                for (int j = 0; j < 8; ++j) rb[j] = Bs[kk][tc + j];
#pragma unroll
                for (int i = 0; i < 8; ++i)
#pragma unroll
                    for (int j = 0; j < 8; ++j)
                        acc[i][j] = fmaf(ra[i], rb[j], acc[i][j]);
            }
        }
#pragma unroll
        for (int i = 0; i < 8; ++i)
#pragma unroll
            for (int j = 0; j < 8; ++j) {
                float v = acc[i][j] + bk[h * CDIM + col0 + tc + j];
                oacc[i][j] += fmaxf(v, 0.f);
            }
    }

#pragma unroll
    for (int i = 0; i < 8; ++i) {
        float* Op = out + (size_t)(row0 + tr + i) * Nn + (col0 + tc);
#pragma unroll
        for (int j = 0; j < 8; ++j) Op[j] = oacc[i][j] * 0.125f;
    }
}

// ---------------------------------------------------------------------------
extern "C" void kernel_launch(void* const* d_in, const int* in_sizes, int n_in,
                              void* d_out, int out_size)
{
    (void)in_sizes; (void)n_in; (void)out_size;
    const float* x  = (const float*)d_in[0];
    const float* Wt = (const float*)d_in[1];
    const float* bt = (const float*)d_in[2];
    const float* Wp = (const float*)d_in[3];
    const float* bp = (const float*)d_in[4];
    const float* Wk = (const float*)d_in[5];
    const float* bk = (const float*)d_in[6];
    float* out = (float*)d_out;

    float *Q, *Kp, *S, *Y;
    cudaGetSymbolAddress((void**)&Q,  g_Q);
    cudaGetSymbolAddress((void**)&Kp, g_Kp);
    cudaGetSymbolAddress((void**)&S,  g_S);
    cudaGetSymbolAddress((void**)&Y,  g_Y);

    const dim3 blk(256);

    // 1) Q = x @ W_theta + b_theta ; K = x @ W_phi + b_phi
    sgemm_nn<<<dim3(CDIM / 128, NTOK / 128), blk>>>(x, Wt, bt, Q, NTOK, CDIM, CDIM);
    sgemm_nn<<<dim3(CDIM / 128, NTOK / 128), blk>>>(x, Wp, bp, Kp, NTOK, CDIM, CDIM);

    // 2) S = Q @ K^T
    sgemm_nt<<<dim3(NTOK / 128, NTOK / 128), blk>>>(Q, Kp, S, NTOK, NTOK, CDIM);

    // 3) row softmax in place
    softmax_rows<<<NTOK, blk>>>(S);

    // 4) Y = adj @ x   (factorization: adj @ (x@Wk[h]+b) == (adj@x)@Wk[h]+b)
    sgemm_nn<<<dim3(CDIM / 128, NTOK / 128), blk>>>(S, x, nullptr, Y, NTOK, CDIM, NTOK);

    // 5) out = mean_h relu(Y @ Wk[h] + bk[h])
    heads_kernel<<<dim3(CDIM / 128, NTOK / 128), blk>>>(Y, Wk, bk, out);
}

// round 4
// speedup vs baseline: 1.3032x; 1.2997x over previous
#include <cuda_runtime.h>
#include <cstdint>
#include <cstddef>

#define NTOK 8192
#define CD   512
#define NH   8

#define BM 128
#define BN 128
#define BK 16
#define KP 20                      // padded row length (floats) — conflict-free
#define STAGES 3
#define STAGE_FLOATS (4 * 128 * KP)   // Ahi,Alo,Bhi,Blo tiles: 10240 floats
#define SMEM_BYTES (STAGES * STAGE_FLOATS * 4)

// ---------------- scratch ----------------------------------------------------
__device__ float g_xhi[NTOK*CD],  g_xlo[NTOK*CD];
__device__ float g_xThi[CD*NTOK], g_xTlo[CD*NTOK];
__device__ float g_WtThi[CD*CD],  g_WtTlo[CD*CD];
__device__ float g_WpThi[CD*CD],  g_WpTlo[CD*CD];
__device__ float g_WkThi[NH*CD*CD], g_WkTlo[NH*CD*CD];
__device__ float g_Qhi[NTOK*CD],  g_Qlo[NTOK*CD];
__device__ float g_Khi[NTOK*CD],  g_Klo[NTOK*CD];
__device__ float g_S[(size_t)NTOK*NTOK];
__device__ float g_Plo[(size_t)NTOK*NTOK];
__device__ float g_Yhi[NTOK*CD],  g_Ylo[NTOK*CD];
__device__ float g_Z[(size_t)NH*NTOK*CD];

// ---------------- helpers ----------------------------------------------------
__device__ __forceinline__ float tf32_hi(float v) {
    uint32_t u; asm("cvt.rna.tf32.f32 %0, %1;" : "=r"(u) : "f"(v));
    return __uint_as_float(u);
}
__device__ __forceinline__ uint32_t smem_u32(const void* p) {
    uint32_t a;
    asm("{ .reg .u64 t; cvta.to.shared.u64 t, %1; cvt.u32.u64 %0, t; }" : "=r"(a) : "l"(p));
    return a;
}
__device__ __forceinline__ void cp16(uint32_t d, const void* s) {
    asm volatile("cp.async.cg.shared.global [%0], [%1], 16;" :: "r"(d), "l"(s));
}
__device__ __forceinline__ void cp_commit() { asm volatile("cp.async.commit_group;"); }
__device__ __forceinline__ void cp_wait2()  { asm volatile("cp.async.wait_group 2;"); }

__device__ __forceinline__ void mma_tf32(float& c0, float& c1, float& c2, float& c3,
                                         uint32_t a0, uint32_t a1, uint32_t a2, uint32_t a3,
                                         uint32_t b0, uint32_t b1) {
    asm volatile(
        "mma.sync.aligned.m16n8k8.row.col.f32.tf32.tf32.f32 "
        "{%0,%1,%2,%3}, {%4,%5,%6,%7}, {%8,%9}, {%0,%1,%2,%3};"
        : "+f"(c0), "+f"(c1), "+f"(c2), "+f"(c3)
        : "r"(a0), "r"(a1), "r"(a2), "r"(a3), "r"(b0), "r"(b1));
}

// ---------------- tf32x3 tensor GEMM: C[8192, N] = A @ B^T ------------------
// A[8192, K] hi/lo, B[N, K] hi/lo, all K-major.
// mode 0: store fp32->C0   1: split->C0/C1   2: +bias split   3: +bias store
__global__ __launch_bounds__(256, 1)
void gemm_tc(const float* __restrict__ Ahi, const float* __restrict__ Alo,
             const float* __restrict__ Bhi, const float* __restrict__ Blo,
             int K, int N, float* __restrict__ C0, float* __restrict__ C1,
             const float* __restrict__ bias, int mode,
             size_t strB, size_t strBias, size_t strC)
{
    extern __shared__ float sm[];
    const int tid  = threadIdx.x;
    const int wid  = tid >> 5, lane = tid & 31;
    const int gid  = lane >> 2, tig = lane & 3;
    const int wm   = wid & 3, wn = wid >> 2;       // warp grid 4x2 (M x N)

    const int z = blockIdx.z;
    Bhi += (size_t)z * strB;  Blo += (size_t)z * strB;
    if (bias) bias += (size_t)z * strBias;
    C0 += (size_t)z * strC;   if (C1) C1 += (size_t)z * strC;

    // supertile swizzle (GROUP_M = 8)
    const int mt_n = NTOK / BM, nt_n = N / BN;
    int tile = blockIdx.x;
    int npg  = 8 * nt_n;
    int grp  = tile / npg;
    int fm   = grp * 8;
    int gsz  = min(mt_n - fm, 8);
    int m_t  = fm + (tile % npg) % gsz;
    int n_t  = (tile % npg) / gsz;
    const int row0 = m_t * BM, col0 = n_t * BN;

    const uint32_t smb = smem_u32(sm);
    const float* srcs[4] = { Ahi, Alo, Bhi, Blo };
    const int offs[4] = { row0, row0, col0, col0 };

    const int NC = K / BK;

    // ---- async loader for one chunk into stage s (8 cp16 per thread) ----
    auto load_chunk = [&](int c, int s) {
        const int k0 = c * BK;
#pragma unroll
        for (int i = 0; i < 8; ++i) {
            int id  = i * 256 + tid;
            int mat = id >> 9;
            int r   = (id >> 2) & 127;
            int c4  = id & 3;
            uint32_t dst = smb + (uint32_t)(s * STAGE_FLOATS + mat * 2560 + r * KP + c4 * 4) * 4u;
            cp16(dst, srcs[mat] + (size_t)(offs[mat] + r) * K + k0 + c4 * 4);
        }
    };

    float acc[2][8][4];
#pragma unroll
    for (int mt = 0; mt < 2; ++mt)
#pragma unroll
        for (int nt = 0; nt < 8; ++nt)
#pragma unroll
            for (int q = 0; q < 4; ++q) acc[mt][nt][q] = 0.f;

    // prologue
    load_chunk(0, 0); cp_commit();
    load_chunk(1, 1); cp_commit();
    if (NC > 2) load_chunk(2, 2);
    cp_commit();

#pragma unroll 1
    for (int c = 0; c < NC; ++c) {
        const int s = c % STAGES;
        cp_wait2();
        __syncthreads();

        const uint32_t* sAhi = (const uint32_t*)(sm + s * STAGE_FLOATS);
        const uint32_t* sAlo = sAhi + 2560;
        const uint32_t* sBhi = sAhi + 5120;
        const uint32_t* sBlo = sAhi + 7680;

#pragma unroll
        for (int ks = 0; ks < 2; ++ks) {
            const int kk = ks * 8 + tig;
            uint32_t ah[2][4], al[2][4];
#pragma unroll
            for (int mt = 0; mt < 2; ++mt) {
                int r = wm * 32 + mt * 16 + gid;
                ah[mt][0] = sAhi[r * KP + kk];       ah[mt][1] = sAhi[(r + 8) * KP + kk];
                ah[mt][2] = sAhi[r * KP + kk + 4];   ah[mt][3] = sAhi[(r + 8) * KP + kk + 4];
                al[mt][0] = sAlo[r * KP + kk];       al[mt][1] = sAlo[(r + 8) * KP + kk];
                al[mt][2] = sAlo[r * KP + kk + 4];   al[mt][3] = sAlo[(r + 8) * KP + kk + 4];
            }
            uint32_t bh[8][2], bl[8][2];
#pragma unroll
            for (int nt = 0; nt < 8; ++nt) {
                int cn = wn * 64 + nt * 8 + gid;
                bh[nt][0] = sBhi[cn * KP + kk];  bh[nt][1] = sBhi[cn * KP + kk + 4];
                bl[nt][0] = sBlo[cn * KP + kk];  bl[nt][1] = sBlo[cn * KP + kk + 4];
            }
#pragma unroll
            for (int mt = 0; mt < 2; ++mt)
#pragma unroll
                for (int nt = 0; nt < 8; ++nt) {
                    float* a = acc[mt][nt];
                    mma_tf32(a[0], a[1], a[2], a[3],
                             ah[mt][0], ah[mt][1], ah[mt][2], ah[mt][3],
                             bh[nt][0], bh[nt][1]);
                    mma_tf32(a[0], a[1], a[2], a[3],
                             ah[mt][0], ah[mt][1], ah[mt][2], ah[mt][3],
                             bl[nt][0], bl[nt][1]);
                    mma_tf32(a[0], a[1], a[2], a[3],
                             al[mt][0], al[mt][1], al[mt][2], al[mt][3],
                             bh[nt][0], bh[nt][1]);
                }
        }
        __syncthreads();
        if (c + 3 < NC) load_chunk(c + 3, s);
        cp_commit();                 // always commit to keep wait_group math valid
    }

    // ---- epilogue ----
#pragma unroll
    for (int mt = 0; mt < 2; ++mt) {
#pragma unroll
        for (int nt = 0; nt < 8; ++nt) {
            int row = row0 + wm * 32 + mt * 16 + gid;
            int col = col0 + wn * 64 + nt * 8 + tig * 2;
            float v0 = acc[mt][nt][0], v1 = acc[mt][nt][1];
            float v2 = acc[mt][nt][2], v3 = acc[mt][nt][3];
            if (mode >= 2) {
                float b0 = bias[col], b1 = bias[col + 1];
                v0 += b0; v1 += b1; v2 += b0; v3 += b1;
            }
            size_t ad0 = (size_t)row * N + col;
            size_t ad1 = (size_t)(row + 8) * N + col;
            if (mode == 1 || mode == 2) {
                float h0 = tf32_hi(v0), h1 = tf32_hi(v1), h2 = tf32_hi(v2), h3 = tf32_hi(v3);
                float2 hh0 = { h0, h1 }, hh1 = { h2, h3 };
                float2 ll0 = { v0 - h0, v1 - h1 }, ll1 = { v2 - h2, v3 - h3 };
                *(float2*)(C0 + ad0) = hh0;  *(float2*)(C0 + ad1) = hh1;
                *(float2*)(C1 + ad0) = ll0;  *(float2*)(C1 + ad1) = ll1;
            } else {
                float2 o0 = { v0, v1 }, o1 = { v2, v3 };
                *(float2*)(C0 + ad0) = o0;   *(float2*)(C0 + ad1) = o1;
            }
        }
    }
}

// ---------------- prep / softmax / reduce -----------------------------------
__global__ void split_arr(const float* __restrict__ s, float* __restrict__ hi,
                          float* __restrict__ lo, size_t n)
{
    for (size_t i = (size_t)blockIdx.x * blockDim.x + threadIdx.x; i < n;
         i += (size_t)gridDim.x * blockDim.x) {
        float v = s[i], h = tf32_hi(v);
        hi[i] = h; lo[i] = v - h;
    }
}
__global__ void transpose_split(const float* __restrict__ src, float* __restrict__ dhi,
                                float* __restrict__ dlo, int R, int C)
{
    __shared__ float t[32][33];
    const size_t bo = (size_t)blockIdx.z * R * C;
    const float* s = src + bo;
    float* oh = dhi + bo; float* ol = dlo + bo;
    int c0 = blockIdx.x * 32, r0 = blockIdx.y * 32;
    int tx = threadIdx.x, ty = threadIdx.y;
#pragma unroll
    for (int i = 0; i < 4; ++i)
        t[ty + i*8][tx] = s[(size_t)(r0 + ty + i*8) * C + c0 + tx];
    __syncthreads();
#pragma unroll
    for (int i = 0; i < 4; ++i) {
        float v = t[tx][ty + i*8], h = tf32_hi(v);
        size_t ad = (size_t)(c0 + ty + i*8) * R + r0 + tx;
        oh[ad] = h; ol[ad] = v - h;
    }
}
__device__ __forceinline__ float wmax(float v) {
#pragma unroll
    for (int o = 16; o > 0; o >>= 1) v = fmaxf(v, __shfl_xor_sync(0xffffffffu, v, o));
    return v;
}
__device__ __forceinline__ float wsum(float v) {
#pragma unroll
    for (int o = 16; o > 0; o >>= 1) v += __shfl_xor_sync(0xffffffffu, v, o);
    return v;
}
__global__ __launch_bounds__(256, 4)
void softmax_split(float* __restrict__ S, float* __restrict__ Plo)
{
    float* r = S + (size_t)blockIdx.x * NTOK;
    float* pl = Plo + (size_t)blockIdx.x * NTOK;
    const int tid = threadIdx.x;
    __shared__ float red[8];
    float v[32];
    float m = -3.4e38f;
#pragma unroll
    for (int i = 0; i < 32; ++i) { v[i] = r[i*256 + tid]; m = fmaxf(m, v[i]); }
    m = wmax(m);
    if ((tid & 31) == 0) red[tid >> 5] = m;
    __syncthreads();
    { float t = red[tid & 7];
      t = fmaxf(t, __shfl_xor_sync(0xffffffffu, t, 1));
      t = fmaxf(t, __shfl_xor_sync(0xffffffffu, t, 2));
      t = fmaxf(t, __shfl_xor_sync(0xffffffffu, t, 4)); m = t; }
    float s = 0.f;
#pragma unroll
    for (int i = 0; i < 32; ++i) { v[i] = __expf(v[i] - m); s += v[i]; }
    s = wsum(s);
    __syncthreads();
    if ((tid & 31) == 0) red[tid >> 5] = s;
    __syncthreads();
    { float t = red[tid & 7];
      t += __shfl_xor_sync(0xffffffffu, t, 1);
      t += __shfl_xor_sync(0xffffffffu, t, 2);
      t += __shfl_xor_sync(0xffffffffu, t, 4); s = t; }
    const float inv = 1.f / s;
#pragma unroll
    for (int i = 0; i < 32; ++i) {
        float p = v[i] * inv, h = tf32_hi(p);
        r[i*256 + tid] = h;
        pl[i*256 + tid] = p - h;
    }
}
__global__ void reduce_heads(const float* __restrict__ Z, float* __restrict__ out)
{
    const size_t n = (size_t)NTOK * CD / 4;
    const size_t str = (size_t)NTOK * CD / 4;
    const float4* z = (const float4*)Z;
    for (size_t i = (size_t)blockIdx.x * blockDim.x + threadIdx.x; i < n;
         i += (size_t)gridDim.x * blockDim.x) {
        float4 a = { 0.f, 0.f, 0.f, 0.f };
#pragma unroll
        for (int h = 0; h < NH; ++h) {
            float4 v = z[h * str + i];
            a.x += fmaxf(v.x, 0.f); a.y += fmaxf(v.y, 0.f);
            a.z += fmaxf(v.z, 0.f); a.w += fmaxf(v.w, 0.f);
        }
        a.x *= 0.125f; a.y *= 0.125f; a.z *= 0.125f; a.w *= 0.125f;
        ((float4*)out)[i] = a;
    }
}

// ---------------- host -------------------------------------------------------
extern "C" void kernel_launch(void* const* d_in, const int* in_sizes, int n_in,
                              void* d_out, int out_size)
{
    (void)in_sizes; (void)n_in; (void)out_size;
    const float* x  = (const float*)d_in[0];
    const float* Wt = (const float*)d_in[1];
    const float* bt = (const float*)d_in[2];
    const float* Wp = (const float*)d_in[3];
    const float* bp = (const float*)d_in[4];
    const float* Wk = (const float*)d_in[5];
    const float* bk = (const float*)d_in[6];
    float* out = (float*)d_out;

    float *xhi,*xlo,*xThi,*xTlo,*WtThi,*WtTlo,*WpThi,*WpTlo,*WkThi,*WkTlo;
    float *Qhi,*Qlo,*Khi,*Klo,*S,*Plo,*Yhi,*Ylo,*Z;
    cudaGetSymbolAddress((void**)&xhi, g_xhi);   cudaGetSymbolAddress((void**)&xlo, g_xlo);
    cudaGetSymbolAddress((void**)&xThi, g_xThi); cudaGetSymbolAddress((void**)&xTlo, g_xTlo);
    cudaGetSymbolAddress((void**)&WtThi, g_WtThi); cudaGetSymbolAddress((void**)&WtTlo, g_WtTlo);
    cudaGetSymbolAddress((void**)&WpThi, g_WpThi); cudaGetSymbolAddress((void**)&WpTlo, g_WpTlo);
    cudaGetSymbolAddress((void**)&WkThi, g_WkThi); cudaGetSymbolAddress((void**)&WkTlo, g_WkTlo);
    cudaGetSymbolAddress((void**)&Qhi, g_Qhi);   cudaGetSymbolAddress((void**)&Qlo, g_Qlo);
    cudaGetSymbolAddress((void**)&Khi, g_Khi);   cudaGetSymbolAddress((void**)&Klo, g_Klo);
    cudaGetSymbolAddress((void**)&S, g_S);       cudaGetSymbolAddress((void**)&Plo, g_Plo);
    cudaGetSymbolAddress((void**)&Yhi, g_Yhi);   cudaGetSymbolAddress((void**)&Ylo, g_Ylo);
    cudaGetSymbolAddress((void**)&Z, g_Z);

    cudaFuncSetAttribute(gemm_tc, cudaFuncAttributeMaxDynamicSharedMemorySize, SMEM_BYTES);

    // prep: splits + transposes
    split_arr<<<512, 256>>>(x, xhi, xlo, (size_t)NTOK * CD);
    transpose_split<<<dim3(CD/32, NTOK/32, 1), dim3(32, 8)>>>(x, xThi, xTlo, NTOK, CD);
    transpose_split<<<dim3(CD/32, CD/32, 1), dim3(32, 8)>>>(Wt, WtThi, WtTlo, CD, CD);
    transpose_split<<<dim3(CD/32, CD/32, 1), dim3(32, 8)>>>(Wp, WpThi, WpTlo, CD, CD);
    transpose_split<<<dim3(CD/32, CD/32, NH), dim3(32, 8)>>>(Wk, WkThi, WkTlo, CD, CD);

    const int mt = NTOK / BM;            // 64
    // Q = x@Wt + bt (split), K = x@Wp + bp (split)
    gemm_tc<<<mt * (CD/BN), 256, SMEM_BYTES>>>(xhi, xlo, WtThi, WtTlo, CD, CD,
                                               Qhi, Qlo, bt, 2, 0, 0, 0);
    gemm_tc<<<mt * (CD/BN), 256, SMEM_BYTES>>>(xhi, xlo, WpThi, WpTlo, CD, CD,
                                               Khi, Klo, bp, 2, 0, 0, 0);
    // S = Q @ K^T
    gemm_tc<<<mt * (NTOK/BN), 256, SMEM_BYTES>>>(Qhi, Qlo, Khi, Klo, CD, NTOK,
                                                 S, nullptr, nullptr, 0, 0, 0, 0);
    // softmax rows -> hi (in place) / lo
    softmax_split<<<NTOK, 256>>>(S, Plo);
    // Y = P @ x (split)
    gemm_tc<<<mt * (CD/BN), 256, SMEM_BYTES>>>(S, Plo, xThi, xTlo, NTOK, CD,
                                               Yhi, Ylo, nullptr, 1, 0, 0, 0);
    // Z[h] = Y @ Wk[h]^T + bk[h]
    gemm_tc<<<dim3(mt * (CD/BN), 1, NH), 256, SMEM_BYTES>>>(
        Yhi, Ylo, WkThi, WkTlo, CD, CD, Z, nullptr, bk, 3,
        (size_t)CD * CD, (size_t)CD, (size_t)NTOK * CD);
    // out = mean_h relu(Z)
    reduce_heads<<<512, 256>>>(Z, out);
}

// round 5
// speedup vs baseline: 2.4588x; 1.8868x over previous
#include <cuda_runtime.h>
#include <cuda_bf16.h>
#include <cstdint>
#include <cstddef>

#define NTOK 8192
#define CD   512
#define NH   8

#define BM 128
#define BN 128
#define BK 32                      // K halves per chunk
#define KPW 20                     // padded row stride in 32-bit words (80 B)
#define STAGES 3
#define MAT_WORDS (128 * KPW)          // 2560
#define STAGE_WORDS (4 * MAT_WORDS)    // 10240
#define SMEM_BYTES (STAGES * STAGE_WORDS * 4)   // 122880

typedef __nv_bfloat16 bf16;

// ---------------- scratch ----------------------------------------------------
__device__ bf16 g_xhi[NTOK*CD],  g_xlo[NTOK*CD];
__device__ bf16 g_xThi[CD*NTOK], g_xTlo[CD*NTOK];
__device__ bf16 g_WtThi[CD*CD],  g_WtTlo[CD*CD];
__device__ bf16 g_WpThi[CD*CD],  g_WpTlo[CD*CD];
__device__ bf16 g_WkThi[NH*CD*CD], g_WkTlo[NH*CD*CD];
__device__ bf16 g_Qhi[NTOK*CD],  g_Qlo[NTOK*CD];
__device__ bf16 g_Khi[NTOK*CD],  g_Klo[NTOK*CD];
__device__ float g_S[(size_t)NTOK*NTOK];
__device__ bf16 g_Phi[(size_t)NTOK*NTOK];
__device__ bf16 g_Plo[(size_t)NTOK*NTOK];
__device__ bf16 g_Yhi[NTOK*CD],  g_Ylo[NTOK*CD];
__device__ float g_Z[(size_t)NH*NTOK*CD];

// ---------------- helpers ----------------------------------------------------
__device__ __forceinline__ uint32_t smem_u32(const void* p) {
    uint32_t a;
    asm("{ .reg .u64 t; cvta.to.shared.u64 t, %1; cvt.u32.u64 %0, t; }" : "=r"(a) : "l"(p));
    return a;
}
__device__ __forceinline__ void cp16(uint32_t d, const void* s) {
    asm volatile("cp.async.cg.shared.global [%0], [%1], 16;" :: "r"(d), "l"(s));
}
__device__ __forceinline__ void cp_commit() { asm volatile("cp.async.commit_group;"); }
__device__ __forceinline__ void cp_wait2()  { asm volatile("cp.async.wait_group 2;"); }

__device__ __forceinline__ void mma_bf16(float& c0, float& c1, float& c2, float& c3,
                                         uint32_t a0, uint32_t a1, uint32_t a2, uint32_t a3,
                                         uint32_t b0, uint32_t b1) {
    asm volatile(
        "mma.sync.aligned.m16n8k16.row.col.f32.bf16.bf16.f32 "
        "{%0,%1,%2,%3}, {%4,%5,%6,%7}, {%8,%9}, {%0,%1,%2,%3};"
        : "+f"(c0), "+f"(c1), "+f"(c2), "+f"(c3)
        : "r"(a0), "r"(a1), "r"(a2), "r"(a3), "r"(b0), "r"(b1));
}

// ---------------- bf16x3 tensor GEMM: C[8192, N] = A @ B^T ------------------
// A[8192, K] hi/lo bf16, B[N, K] hi/lo bf16, all K-major.
// mode 0: fp32 -> C0    1: split bf16 -> C0/C1
// mode 2: +bias, split bf16 -> C0/C1    3: +bias, fp32 -> C0
__global__ __launch_bounds__(256, 1)
void gemm_tc(const bf16* __restrict__ Ahi, const bf16* __restrict__ Alo,
             const bf16* __restrict__ Bhi, const bf16* __restrict__ Blo,
             int K, int N, void* __restrict__ C0v, void* __restrict__ C1v,
             const float* __restrict__ bias, int mode,
             size_t strB, size_t strBias, size_t strC)
{
    extern __shared__ float sm[];
    const int tid  = threadIdx.x;
    const int wid  = tid >> 5, lane = tid & 31;
    const int gid  = lane >> 2, tig = lane & 3;
    const int wm   = wid & 3, wn = wid >> 2;       // warp grid 4x2 (M x N)

    const int z = blockIdx.z;
    Bhi += (size_t)z * strB;  Blo += (size_t)z * strB;
    if (bias) bias += (size_t)z * strBias;
    const size_t zC = (size_t)z * strC;

    // supertile swizzle (GROUP_M = 8)
    const int mt_n = NTOK / BM, nt_n = N / BN;
    int tile = blockIdx.x;
    int npg  = 8 * nt_n;
    int grp  = tile / npg;
    int fm   = grp * 8;
    int gsz  = min(mt_n - fm, 8);
    int m_t  = fm + (tile % npg) % gsz;
    int n_t  = (tile % npg) / gsz;
    const int row0 = m_t * BM, col0 = n_t * BN;

    const uint32_t smb = smem_u32(sm);
    const bf16* srcs[4] = { Ahi, Alo, Bhi, Blo };
    const int offs[4] = { row0, row0, col0, col0 };

    const int NC = K / BK;

    // ---- async loader: one chunk -> stage s (8 cp16 per thread) ----
    auto load_chunk = [&](int c, int s) {
        const int k0 = c * BK;
#pragma unroll
        for (int i = 0; i < 8; ++i) {
            int id  = i * 256 + tid;
            int mat = id >> 9;
            int r   = (id >> 2) & 127;
            int c4  = id & 3;
            uint32_t dst = smb + (uint32_t)(s * STAGE_WORDS + mat * MAT_WORDS + r * KPW) * 4u
                         + (uint32_t)c4 * 16u;
            cp16(dst, srcs[mat] + (size_t)(offs[mat] + r) * K + k0 + c4 * 8);
        }
    };

    float acc[2][8][4];
#pragma unroll
    for (int mt = 0; mt < 2; ++mt)
#pragma unroll
        for (int nt = 0; nt < 8; ++nt)
#pragma unroll
            for (int q = 0; q < 4; ++q) acc[mt][nt][q] = 0.f;

    load_chunk(0, 0); cp_commit();
    load_chunk(1, 1); cp_commit();
    if (NC > 2) load_chunk(2, 2);
    cp_commit();

#pragma unroll 1
    for (int c = 0; c < NC; ++c) {
        const int s = c % STAGES;
        cp_wait2();
        __syncthreads();

        const uint32_t* sAhi = (const uint32_t*)(sm + s * STAGE_WORDS);
        const uint32_t* sAlo = sAhi + MAT_WORDS;
        const uint32_t* sBhi = sAhi + 2 * MAT_WORDS;
        const uint32_t* sBlo = sAhi + 3 * MAT_WORDS;

#pragma unroll
        for (int ks = 0; ks < 2; ++ks) {
            const int kw = ks * 8 + tig;            // word offset within row
            uint32_t ah[2][4], al[2][4];
#pragma unroll
            for (int mt = 0; mt < 2; ++mt) {
                int r = wm * 32 + mt * 16 + gid;
                ah[mt][0] = sAhi[r * KPW + kw];       ah[mt][1] = sAhi[(r + 8) * KPW + kw];
                ah[mt][2] = sAhi[r * KPW + kw + 4];   ah[mt][3] = sAhi[(r + 8) * KPW + kw + 4];
                al[mt][0] = sAlo[r * KPW + kw];       al[mt][1] = sAlo[(r + 8) * KPW + kw];
                al[mt][2] = sAlo[r * KPW + kw + 4];   al[mt][3] = sAlo[(r + 8) * KPW + kw + 4];
            }
            uint32_t bh[8][2], bl[8][2];
#pragma unroll
            for (int nt = 0; nt < 8; ++nt) {
                int cn = wn * 64 + nt * 8 + gid;
                bh[nt][0] = sBhi[cn * KPW + kw];  bh[nt][1] = sBhi[cn * KPW + kw + 4];
                bl[nt][0] = sBlo[cn * KPW + kw];  bl[nt][1] = sBlo[cn * KPW + kw + 4];
            }
#pragma unroll
            for (int mt = 0; mt < 2; ++mt)
#pragma unroll
                for (int nt = 0; nt < 8; ++nt) {
                    float* a = acc[mt][nt];
                    mma_bf16(a[0], a[1], a[2], a[3],
                             ah[mt][0], ah[mt][1], ah[mt][2], ah[mt][3],
                             bh[nt][0], bh[nt][1]);
                    mma_bf16(a[0], a[1], a[2], a[3],
                             ah[mt][0], ah[mt][1], ah[mt][2], ah[mt][3],
                             bl[nt][0], bl[nt][1]);
                    mma_bf16(a[0], a[1], a[2], a[3],
                             al[mt][0], al[mt][1], al[mt][2], al[mt][3],
                             bh[nt][0], bh[nt][1]);
                }
        }
        __syncthreads();
        if (c + 3 < NC) load_chunk(c + 3, s);
        cp_commit();
    }

    // ---- epilogue ----
#pragma unroll
    for (int mt = 0; mt < 2; ++mt) {
#pragma unroll
        for (int nt = 0; nt < 8; ++nt) {
            int row = row0 + wm * 32 + mt * 16 + gid;
            int col = col0 + wn * 64 + nt * 8 + tig * 2;
            float v0 = acc[mt][nt][0], v1 = acc[mt][nt][1];
            float v2 = acc[mt][nt][2], v3 = acc[mt][nt][3];
            if (mode >= 2) {
                float b0 = bias[col], b1 = bias[col + 1];
                v0 += b0; v1 += b1; v2 += b0; v3 += b1;
            }
            size_t ad0 = (size_t)row * N + col;
            size_t ad1 = (size_t)(row + 8) * N + col;
            if (mode == 1 || mode == 2) {
                bf16* o0 = (bf16*)C0v + zC;
                bf16* o1 = (bf16*)C1v + zC;
                bf16 h0 = __float2bfloat16(v0), h1 = __float2bfloat16(v1);
                bf16 h2 = __float2bfloat16(v2), h3 = __float2bfloat16(v3);
                __nv_bfloat162 hh0 = { h0, h1 }, hh1 = { h2, h3 };
                __nv_bfloat162 ll0 = { __float2bfloat16(v0 - __bfloat162float(h0)),
                                       __float2bfloat16(v1 - __bfloat162float(h1)) };
                __nv_bfloat162 ll1 = { __float2bfloat16(v2 - __bfloat162float(h2)),
                                       __float2bfloat16(v3 - __bfloat162float(h3)) };
                *(__nv_bfloat162*)(o0 + ad0) = hh0;  *(__nv_bfloat162*)(o0 + ad1) = hh1;
                *(__nv_bfloat162*)(o1 + ad0) = ll0;  *(__nv_bfloat162*)(o1 + ad1) = ll1;
            } else {
                float* o = (float*)C0v + zC;
                float2 q0 = { v0, v1 }, q1 = { v2, v3 };
                *(float2*)(o + ad0) = q0;  *(float2*)(o + ad1) = q1;
            }
        }
    }
}

// ---------------- prep / softmax / reduce -----------------------------------
__global__ void split_arr(const float* __restrict__ s, bf16* __restrict__ hi,
                          bf16* __restrict__ lo, size_t n)
{
    for (size_t i = (size_t)blockIdx.x * blockDim.x + threadIdx.x; i < n;
         i += (size_t)gridDim.x * blockDim.x) {
        float v = s[i];
        bf16 h = __float2bfloat16(v);
        hi[i] = h;
        lo[i] = __float2bfloat16(v - __bfloat162float(h));
    }
}
__global__ void transpose_split(const float* __restrict__ src, bf16* __restrict__ dhi,
                                bf16* __restrict__ dlo, int R, int C)
{
    __shared__ float t[32][33];
    const size_t bo = (size_t)blockIdx.z * R * C;
    const float* s = src + bo;
    bf16* oh = dhi + bo; bf16* ol = dlo + bo;
    int c0 = blockIdx.x * 32, r0 = blockIdx.y * 32;
    int tx = threadIdx.x, ty = threadIdx.y;
#pragma unroll
    for (int i = 0; i < 4; ++i)
        t[ty + i*8][tx] = s[(size_t)(r0 + ty + i*8) * C + c0 + tx];
    __syncthreads();
#pragma unroll
    for (int i = 0; i < 4; ++i) {
        float v = t[tx][ty + i*8];
        bf16 h = __float2bfloat16(v);
        size_t ad = (size_t)(c0 + ty + i*8) * R + r0 + tx;
        oh[ad] = h;
        ol[ad] = __float2bfloat16(v - __bfloat162float(h));
    }
}
__device__ __forceinline__ float wmax(float v) {
#pragma unroll
    for (int o = 16; o > 0; o >>= 1) v = fmaxf(v, __shfl_xor_sync(0xffffffffu, v, o));
    return v;
}
__device__ __forceinline__ float wsum(float v) {
#pragma unroll
    for (int o = 16; o > 0; o >>= 1) v += __shfl_xor_sync(0xffffffffu, v, o);
    return v;
}
__global__ __launch_bounds__(256, 4)
void softmax_split(const float* __restrict__ S, bf16* __restrict__ Phi,
                   bf16* __restrict__ Plo)
{
    const float* r = S + (size_t)blockIdx.x * NTOK;
    bf16* ph = Phi + (size_t)blockIdx.x * NTOK;
    bf16* pl = Plo + (size_t)blockIdx.x * NTOK;
    const int tid = threadIdx.x;
    __shared__ float red[8];
    float v[32];
    float m = -3.4e38f;
#pragma unroll
    for (int i = 0; i < 32; ++i) { v[i] = r[i*256 + tid]; m = fmaxf(m, v[i]); }
    m = wmax(m);
    if ((tid & 31) == 0) red[tid >> 5] = m;
    __syncthreads();
    { float t = red[tid & 7];
      t = fmaxf(t, __shfl_xor_sync(0xffffffffu, t, 1));
      t = fmaxf(t, __shfl_xor_sync(0xffffffffu, t, 2));
      t = fmaxf(t, __shfl_xor_sync(0xffffffffu, t, 4)); m = t; }
    float s = 0.f;
#pragma unroll
    for (int i = 0; i < 32; ++i) { v[i] = __expf(v[i] - m); s += v[i]; }
    s = wsum(s);
    __syncthreads();
    if ((tid & 31) == 0) red[tid >> 5] = s;
    __syncthreads();
    { float t = red[tid & 7];
      t += __shfl_xor_sync(0xffffffffu, t, 1);
      t += __shfl_xor_sync(0xffffffffu, t, 2);
      t += __shfl_xor_sync(0xffffffffu, t, 4); s = t; }
    const float inv = 1.f / s;
#pragma unroll
    for (int i = 0; i < 32; ++i) {
        float p = v[i] * inv;
        bf16 h = __float2bfloat16(p);
        ph[i*256 + tid] = h;
        pl[i*256 + tid] = __float2bfloat16(p - __bfloat162float(h));
    }
}
__global__ void reduce_heads(const float* __restrict__ Z, float* __restrict__ out)
{
    const size_t n = (size_t)NTOK * CD / 4;
    const size_t str = (size_t)NTOK * CD / 4;
    const float4* z = (const float4*)Z;
    for (size_t i = (size_t)blockIdx.x * blockDim.x + threadIdx.x; i < n;
         i += (size_t)gridDim.x * blockDim.x) {
        float4 a = { 0.f, 0.f, 0.f, 0.f };
#pragma unroll
        for (int h = 0; h < NH; ++h) {
            float4 v = z[h * str + i];
            a.x += fmaxf(v.x, 0.f); a.y += fmaxf(v.y, 0.f);
            a.z += fmaxf(v.z, 0.f); a.w += fmaxf(v.w, 0.f);
        }
        a.x *= 0.125f; a.y *= 0.125f; a.z *= 0.125f; a.w *= 0.125f;
        ((float4*)out)[i] = a;
    }
}

// ---------------- host -------------------------------------------------------
extern "C" void kernel_launch(void* const* d_in, const int* in_sizes, int n_in,
                              void* d_out, int out_size)
{
    (void)in_sizes; (void)n_in; (void)out_size;
    const float* x  = (const float*)d_in[0];
    const float* Wt = (const float*)d_in[1];
    const float* bt = (const float*)d_in[2];
    const float* Wp = (const float*)d_in[3];
    const float* bp = (const float*)d_in[4];
    const float* Wk = (const float*)d_in[5];
    const float* bk = (const float*)d_in[6];
    float* out = (float*)d_out;

    bf16 *xhi,*xlo,*xThi,*xTlo,*WtThi,*WtTlo,*WpThi,*WpTlo,*WkThi,*WkTlo;
    bf16 *Qhi,*Qlo,*Khi,*Klo,*Phi,*Plo,*Yhi,*Ylo;
    float *S, *Z;
    cudaGetSymbolAddress((void**)&xhi, g_xhi);   cudaGetSymbolAddress((void**)&xlo, g_xlo);
    cudaGetSymbolAddress((void**)&xThi, g_xThi); cudaGetSymbolAddress((void**)&xTlo, g_xTlo);
    cudaGetSymbolAddress((void**)&WtThi, g_WtThi); cudaGetSymbolAddress((void**)&WtTlo, g_WtTlo);
    cudaGetSymbolAddress((void**)&WpThi, g_WpThi); cudaGetSymbolAddress((void**)&WpTlo, g_WpTlo);
    cudaGetSymbolAddress((void**)&WkThi, g_WkThi); cudaGetSymbolAddress((void**)&WkTlo, g_WkTlo);
    cudaGetSymbolAddress((void**)&Qhi, g_Qhi);   cudaGetSymbolAddress((void**)&Qlo, g_Qlo);
    cudaGetSymbolAddress((void**)&Khi, g_Khi);   cudaGetSymbolAddress((void**)&Klo, g_Klo);
    cudaGetSymbolAddress((void**)&S, g_S);
    cudaGetSymbolAddress((void**)&Phi, g_Phi);   cudaGetSymbolAddress((void**)&Plo, g_Plo);
    cudaGetSymbolAddress((void**)&Yhi, g_Yhi);   cudaGetSymbolAddress((void**)&Ylo, g_Ylo);
    cudaGetSymbolAddress((void**)&Z, g_Z);

    cudaFuncSetAttribute(gemm_tc, cudaFuncAttributeMaxDynamicSharedMemorySize, SMEM_BYTES);

    // prep: splits + transposes
    split_arr<<<512, 256>>>(x, xhi, xlo, (size_t)NTOK * CD);
    transpose_split<<<dim3(CD/32, NTOK/32, 1), dim3(32, 8)>>>(x, xThi, xTlo, NTOK, CD);
    transpose_split<<<dim3(CD/32, CD/32, 1), dim3(32, 8)>>>(Wt, WtThi, WtTlo, CD, CD);
    transpose_split<<<dim3(CD/32, CD/32, 1), dim3(32, 8)>>>(Wp, WpThi, WpTlo, CD, CD);
    transpose_split<<<dim3(CD/32, CD/32, NH), dim3(32, 8)>>>(Wk, WkThi, WkTlo, CD, CD);

    const int mt = NTOK / BM;            // 64
    // Q = x@Wt + bt (split), K = x@Wp + bp (split)
    gemm_tc<<<mt * (CD/BN), 256, SMEM_BYTES>>>(xhi, xlo, WtThi, WtTlo, CD, CD,
                                               Qhi, Qlo, bt, 2, 0, 0, 0);
    gemm_tc<<<mt * (CD/BN), 256, SMEM_BYTES>>>(xhi, xlo, WpThi, WpTlo, CD, CD,
                                               Khi, Klo, bp, 2, 0, 0, 0);
    // S = Q @ K^T  (fp32 logits)
    gemm_tc<<<mt * (NTOK/BN), 256, SMEM_BYTES>>>(Qhi, Qlo, Khi, Klo, CD, NTOK,
                                                 S, nullptr, nullptr, 0, 0, 0, 0);
    // softmax rows -> bf16 hi/lo
    softmax_split<<<NTOK, 256>>>(S, Phi, Plo);
    // Y = P @ x (split)
    gemm_tc<<<mt * (CD/BN), 256, SMEM_BYTES>>>(Phi, Plo, xThi, xTlo, NTOK, CD,
                                               Yhi, Ylo, nullptr, 1, 0, 0, 0);
    // Z[h] = Y @ Wk[h]^T + bk[h]
    gemm_tc<<<dim3(mt * (CD/BN), 1, NH), 256, SMEM_BYTES>>>(
        Yhi, Ylo, WkThi, WkTlo, CD, CD, Z, nullptr, bk, 3,
        (size_t)CD * CD, (size_t)CD, (size_t)NTOK * CD);
    // out = mean_h relu(Z)
    reduce_heads<<<512, 256>>>(Z, out);
}

// round 6
// speedup vs baseline: 3.2058x; 1.3038x over previous
#include <cuda_runtime.h>
#include <cuda_bf16.h>
#include <cuda_fp16.h>
#include <cstdint>
#include <cstddef>

#define NTOK 8192
#define CD   512
#define NH   8

#define BM 128
#define BN 128
#define BK 32                      // 16-bit elements per chunk (16 real k for x3)
#define KPW 20                     // padded row stride in words (80 B)
#define STAGES 2
#define MAT_WORDS (128 * KPW)          // 2560
#define STAGE_WORDS (4 * MAT_WORDS)    // 10240
#define SMEM_BYTES (STAGES * STAGE_WORDS * 4)   // 81920

typedef __nv_bfloat16 bf16;
typedef __half fp16;

// ---------------- scratch ----------------------------------------------------
__device__ bf16 g_xhi[NTOK*CD],  g_xlo[NTOK*CD];
__device__ bf16 g_WtThi[CD*CD],  g_WtTlo[CD*CD];
__device__ bf16 g_WpThi[CD*CD],  g_WpTlo[CD*CD];
__device__ bf16 g_Qhi[NTOK*CD],  g_Qlo[NTOK*CD];
__device__ bf16 g_Khi[NTOK*CD],  g_Klo[NTOK*CD];
__device__ fp16 g_xThi[CD*NTOK], g_xTlo[CD*NTOK];
__device__ fp16 g_WkThi[NH*CD*CD], g_WkTlo[NH*CD*CD];
__device__ fp16 g_Phi[(size_t)NTOK*NTOK];
__device__ fp16 g_Yh[NTOK*CD];
__device__ float g_S[(size_t)NTOK*NTOK];
__device__ float g_Z[(size_t)NH*NTOK*CD];

// ---------------- helpers ----------------------------------------------------
__device__ __forceinline__ uint32_t smem_u32(const void* p) {
    uint32_t a;
    asm("{ .reg .u64 t; cvta.to.shared.u64 t, %1; cvt.u32.u64 %0, t; }" : "=r"(a) : "l"(p));
    return a;
}
__device__ __forceinline__ void cp16(uint32_t d, const void* s) {
    asm volatile("cp.async.cg.shared.global [%0], [%1], 16;" :: "r"(d), "l"(s));
}
__device__ __forceinline__ void cp_commit() { asm volatile("cp.async.commit_group;"); }
__device__ __forceinline__ void cp_wait1()  { asm volatile("cp.async.wait_group 1;"); }

__device__ __forceinline__ void mma_bf(float& c0, float& c1, float& c2, float& c3,
                                       uint32_t a0, uint32_t a1, uint32_t a2, uint32_t a3,
                                       uint32_t b0, uint32_t b1) {
    asm volatile(
        "mma.sync.aligned.m16n8k16.row.col.f32.bf16.bf16.f32 "
        "{%0,%1,%2,%3}, {%4,%5,%6,%7}, {%8,%9}, {%0,%1,%2,%3};"
        : "+f"(c0), "+f"(c1), "+f"(c2), "+f"(c3)
        : "r"(a0), "r"(a1), "r"(a2), "r"(a3), "r"(b0), "r"(b1));
}
__device__ __forceinline__ void mma_fp(float& c0, float& c1, float& c2, float& c3,
                                       uint32_t a0, uint32_t a1, uint32_t a2, uint32_t a3,
                                       uint32_t b0, uint32_t b1) {
    asm volatile(
        "mma.sync.aligned.m16n8k16.row.col.f32.f16.f16.f32 "
        "{%0,%1,%2,%3}, {%4,%5,%6,%7}, {%8,%9}, {%0,%1,%2,%3};"
        : "+f"(c0), "+f"(c1), "+f"(c2), "+f"(c3)
        : "r"(a0), "r"(a1), "r"(a2), "r"(a3), "r"(b0), "r"(b1));
}

// ---------------- tensor GEMM: C[8192, N] = A @ B^T -------------------------
// V=0: bf16x3 (A hi/lo in mats 0/1, B hi/lo in mats 2/3)
// V=1: fp16x2 single-A (A in mat 0, B hi/lo in mats 2/3)
// mode 0: fp32->C0   2: +bias, split bf16->C0/C1   3: +bias, fp32->C0   4: fp16->C0
template<int V>
__global__ __launch_bounds__(256, 2)
void gemm_tc(const uint16_t* __restrict__ Ahi, const uint16_t* __restrict__ Alo,
             const uint16_t* __restrict__ Bhi, const uint16_t* __restrict__ Blo,
             int K, int N, void* __restrict__ C0v, void* __restrict__ C1v,
             const float* __restrict__ bias, int mode,
             size_t strB, size_t strBias, size_t strC)
{
    extern __shared__ float sm[];
    const int tid  = threadIdx.x;
    const int wid  = tid >> 5, lane = tid & 31;
    const int gid  = lane >> 2, tig = lane & 3;
    const int wm   = wid & 3, wn = wid >> 2;

    const int z = blockIdx.z;
    Bhi += (size_t)z * strB;  Blo += (size_t)z * strB;
    if (bias) bias += (size_t)z * strBias;
    const size_t zC = (size_t)z * strC;

    const int mt_n = NTOK / BM, nt_n = N / BN;
    int tile = blockIdx.x;
    int npg  = 8 * nt_n;
    int grp  = tile / npg;
    int fm   = grp * 8;
    int gsz  = min(mt_n - fm, 8);
    int m_t  = fm + (tile % npg) % gsz;
    int n_t  = (tile % npg) / gsz;
    const int row0 = m_t * BM, col0 = n_t * BN;

    const uint32_t smb = smem_u32(sm);
    const int NC = K / BK;

    // loader: V0 -> mats {0:Ahi,1:Alo,2:Bhi,3:Blo}; V1 -> {0:Ahi,2:Bhi,3:Blo}
    auto load_chunk = [&](int c, int s) {
        const int k0 = c * BK;
        const int NIT = (V == 0) ? 8 : 6;
#pragma unroll
        for (int i = 0; i < NIT; ++i) {
            int id  = i * 256 + tid;
            int m3  = id >> 9;                      // 0..NIT/2-1
            int mat = (V == 0) ? m3 : (m3 == 0 ? 0 : m3 + 1);
            const uint16_t* src = (mat == 0) ? Ahi : (mat == 1) ? Alo : (mat == 2) ? Bhi : Blo;
            int base = (mat <= 1) ? row0 : col0;
            int r   = (id >> 2) & 127;
            int c4  = id & 3;
            uint32_t dst = smb + (uint32_t)(s * STAGE_WORDS + mat * MAT_WORDS + r * KPW) * 4u
                         + (uint32_t)c4 * 16u;
            cp16(dst, src + (size_t)(base + r) * K + k0 + c4 * 8);
        }
    };

    float acc[2][8][4];
#pragma unroll
    for (int mt = 0; mt < 2; ++mt)
#pragma unroll
        for (int nt = 0; nt < 8; ++nt)
#pragma unroll
            for (int q = 0; q < 4; ++q) acc[mt][nt][q] = 0.f;

    load_chunk(0, 0); cp_commit();
    if (NC > 1) load_chunk(1, 1);
    cp_commit();

#pragma unroll 1
    for (int c = 0; c < NC; ++c) {
        const int s = c & 1;
        cp_wait1();
        __syncthreads();

        const uint32_t* sA  = (const uint32_t*)(sm + s * STAGE_WORDS);
        const uint32_t* sAl = sA + MAT_WORDS;
        const uint32_t* sBh = sA + 2 * MAT_WORDS;
        const uint32_t* sBl = sA + 3 * MAT_WORDS;

#pragma unroll
        for (int ks = 0; ks < 2; ++ks) {
            const int kw = ks * 8 + tig;
            uint32_t ah[2][4], al[2][4];
#pragma unroll
            for (int mt = 0; mt < 2; ++mt) {
                int r = wm * 32 + mt * 16 + gid;
                ah[mt][0] = sA[r * KPW + kw];       ah[mt][1] = sA[(r + 8) * KPW + kw];
                ah[mt][2] = sA[r * KPW + kw + 4];   ah[mt][3] = sA[(r + 8) * KPW + kw + 4];
                if (V == 0) {
                    al[mt][0] = sAl[r * KPW + kw];     al[mt][1] = sAl[(r + 8) * KPW + kw];
                    al[mt][2] = sAl[r * KPW + kw + 4]; al[mt][3] = sAl[(r + 8) * KPW + kw + 4];
                }
            }
#pragma unroll
            for (int nt = 0; nt < 8; ++nt) {
                int cn = wn * 64 + nt * 8 + gid;
                uint32_t b0 = sBh[cn * KPW + kw], b1 = sBh[cn * KPW + kw + 4];
                uint32_t l0 = sBl[cn * KPW + kw], l1 = sBl[cn * KPW + kw + 4];
#pragma unroll
                for (int mt = 0; mt < 2; ++mt) {
                    float* a = acc[mt][nt];
                    if (V == 0) {
                        mma_bf(a[0], a[1], a[2], a[3],
                               ah[mt][0], ah[mt][1], ah[mt][2], ah[mt][3], b0, b1);
                        mma_bf(a[0], a[1], a[2], a[3],
                               ah[mt][0], ah[mt][1], ah[mt][2], ah[mt][3], l0, l1);
                        mma_bf(a[0], a[1], a[2], a[3],
                               al[mt][0], al[mt][1], al[mt][2], al[mt][3], b0, b1);
                    } else {
                        mma_fp(a[0], a[1], a[2], a[3],
                               ah[mt][0], ah[mt][1], ah[mt][2], ah[mt][3], b0, b1);
                        mma_fp(a[0], a[1], a[2], a[3],
                               ah[mt][0], ah[mt][1], ah[mt][2], ah[mt][3], l0, l1);
                    }
                }
            }
        }
        __syncthreads();
        if (c + 2 < NC) load_chunk(c + 2, s);
        cp_commit();
    }

    // ---- epilogue ----
#pragma unroll
    for (int mt = 0; mt < 2; ++mt) {
#pragma unroll
        for (int nt = 0; nt < 8; ++nt) {
            int row = row0 + wm * 32 + mt * 16 + gid;
            int col = col0 + wn * 64 + nt * 8 + tig * 2;
            float v0 = acc[mt][nt][0], v1 = acc[mt][nt][1];
            float v2 = acc[mt][nt][2], v3 = acc[mt][nt][3];
            if (mode == 2 || mode == 3) {
                float b0 = bias[col], b1 = bias[col + 1];
                v0 += b0; v1 += b1; v2 += b0; v3 += b1;
            }
            size_t ad0 = (size_t)row * N + col;
            size_t ad1 = (size_t)(row + 8) * N + col;
            if (mode == 2) {                       // split bf16
                bf16* o0 = (bf16*)C0v + zC;
                bf16* o1 = (bf16*)C1v + zC;
                bf16 h0 = __float2bfloat16(v0), h1 = __float2bfloat16(v1);
                bf16 h2 = __float2bfloat16(v2), h3 = __float2bfloat16(v3);
                __nv_bfloat162 hh0 = { h0, h1 }, hh1 = { h2, h3 };
                __nv_bfloat162 ll0 = { __float2bfloat16(v0 - __bfloat162float(h0)),
                                       __float2bfloat16(v1 - __bfloat162float(h1)) };
                __nv_bfloat162 ll1 = { __float2bfloat16(v2 - __bfloat162float(h2)),
                                       __float2bfloat16(v3 - __bfloat162float(h3)) };
                *(__nv_bfloat162*)(o0 + ad0) = hh0;  *(__nv_bfloat162*)(o0 + ad1) = hh1;
                *(__nv_bfloat162*)(o1 + ad0) = ll0;  *(__nv_bfloat162*)(o1 + ad1) = ll1;
            } else if (mode == 4) {                // fp16 single
                fp16* o = (fp16*)C0v + zC;
                __half2 q0 = { __float2half(v0), __float2half(v1) };
                __half2 q1 = { __float2half(v2), __float2half(v3) };
                *(__half2*)(o + ad0) = q0;  *(__half2*)(o + ad1) = q1;
            } else {                               // fp32
                float* o = (float*)C0v + zC;
                float2 q0 = { v0, v1 }, q1 = { v2, v3 };
                *(float2*)(o + ad0) = q0;  *(float2*)(o + ad1) = q1;
            }
        }
    }
}

// ---------------- prep / softmax / reduce -----------------------------------
__global__ void split_arr(const float* __restrict__ s, bf16* __restrict__ hi,
                          bf16* __restrict__ lo, size_t n)
{
    for (size_t i = (size_t)blockIdx.x * blockDim.x + threadIdx.x; i < n;
         i += (size_t)gridDim.x * blockDim.x) {
        float v = s[i];
        bf16 h = __float2bfloat16(v);
        hi[i] = h;
        lo[i] = __float2bfloat16(v - __bfloat162float(h));
    }
}
__global__ void transpose_split_bf(const float* __restrict__ src, bf16* __restrict__ dhi,
                                   bf16* __restrict__ dlo, int R, int C)
{
    __shared__ float t[32][33];
    const size_t bo = (size_t)blockIdx.z * R * C;
    const float* s = src + bo;
    bf16* oh = dhi + bo; bf16* ol = dlo + bo;
    int c0 = blockIdx.x * 32, r0 = blockIdx.y * 32;
    int tx = threadIdx.x, ty = threadIdx.y;
#pragma unroll
    for (int i = 0; i < 4; ++i)
        t[ty + i*8][tx] = s[(size_t)(r0 + ty + i*8) * C + c0 + tx];
    __syncthreads();
#pragma unroll
    for (int i = 0; i < 4; ++i) {
        float v = t[tx][ty + i*8];
        bf16 h = __float2bfloat16(v);
        size_t ad = (size_t)(c0 + ty + i*8) * R + r0 + tx;
        oh[ad] = h;
        ol[ad] = __float2bfloat16(v - __bfloat162float(h));
    }
}
__global__ void transpose_split_fp(const float* __restrict__ src, fp16* __restrict__ dhi,
                                   fp16* __restrict__ dlo, int R, int C)
{
    __shared__ float t[32][33];
    const size_t bo = (size_t)blockIdx.z * R * C;
    const float* s = src + bo;
    fp16* oh = dhi + bo; fp16* ol = dlo + bo;
    int c0 = blockIdx.x * 32, r0 = blockIdx.y * 32;
    int tx = threadIdx.x, ty = threadIdx.y;
#pragma unroll
    for (int i = 0; i < 4; ++i)
        t[ty + i*8][tx] = s[(size_t)(r0 + ty + i*8) * C + c0 + tx];
    __syncthreads();
#pragma unroll
    for (int i = 0; i < 4; ++i) {
        float v = t[tx][ty + i*8];
        fp16 h = __float2half(v);
        size_t ad = (size_t)(c0 + ty + i*8) * R + r0 + tx;
        oh[ad] = h;
        ol[ad] = __float2half(v - __half2float(h));
    }
}
__device__ __forceinline__ float wmax(float v) {
#pragma unroll
    for (int o = 16; o > 0; o >>= 1) v = fmaxf(v, __shfl_xor_sync(0xffffffffu, v, o));
    return v;
}
__device__ __forceinline__ float wsum(float v) {
#pragma unroll
    for (int o = 16; o > 0; o >>= 1) v += __shfl_xor_sync(0xffffffffu, v, o);
    return v;
}
__global__ __launch_bounds__(256, 4)
void softmax_fp16(const float* __restrict__ S, fp16* __restrict__ Phi)
{
    const float* r = S + (size_t)blockIdx.x * NTOK;
    fp16* ph = Phi + (size_t)blockIdx.x * NTOK;
    const int tid = threadIdx.x;
    __shared__ float red[8];
    float v[32];
    float m = -3.4e38f;
#pragma unroll
    for (int i = 0; i < 32; ++i) { v[i] = r[i*256 + tid]; m = fmaxf(m, v[i]); }
    m = wmax(m);
    if ((tid & 31) == 0) red[tid >> 5] = m;
    __syncthreads();
    { float t = red[tid & 7];
      t = fmaxf(t, __shfl_xor_sync(0xffffffffu, t, 1));
      t = fmaxf(t, __shfl_xor_sync(0xffffffffu, t, 2));
      t = fmaxf(t, __shfl_xor_sync(0xffffffffu, t, 4)); m = t; }
    float s = 0.f;
#pragma unroll
    for (int i = 0; i < 32; ++i) { v[i] = __expf(v[i] - m); s += v[i]; }
    s = wsum(s);
    __syncthreads();
    if ((tid & 31) == 0) red[tid >> 5] = s;
    __syncthreads();
    { float t = red[tid & 7];
      t += __shfl_xor_sync(0xffffffffu, t, 1);
      t += __shfl_xor_sync(0xffffffffu, t, 2);
      t += __shfl_xor_sync(0xffffffffu, t, 4); s = t; }
    const float inv = 1.f / s;
#pragma unroll
    for (int i = 0; i < 32; ++i)
        ph[i*256 + tid] = __float2half(v[i] * inv);
}
__global__ void reduce_heads(const float* __restrict__ Z, float* __restrict__ out)
{
    const size_t n = (size_t)NTOK * CD / 4;
    const size_t str = (size_t)NTOK * CD / 4;
    const float4* z = (const float4*)Z;
    for (size_t i = (size_t)blockIdx.x * blockDim.x + threadIdx.x; i < n;
         i += (size_t)gridDim.x * blockDim.x) {
        float4 a = { 0.f, 0.f, 0.f, 0.f };
#pragma unroll
        for (int h = 0; h < NH; ++h) {
            float4 v = z[h * str + i];
            a.x += fmaxf(v.x, 0.f); a.y += fmaxf(v.y, 0.f);
            a.z += fmaxf(v.z, 0.f); a.w += fmaxf(v.w, 0.f);
        }
        a.x *= 0.125f; a.y *= 0.125f; a.z *= 0.125f; a.w *= 0.125f;
        ((float4*)out)[i] = a;
    }
}

// ---------------- host -------------------------------------------------------
extern "C" void kernel_launch(void* const* d_in, const int* in_sizes, int n_in,
                              void* d_out, int out_size)
{
    (void)in_sizes; (void)n_in; (void)out_size;
    const float* x  = (const float*)d_in[0];
    const float* Wt = (const float*)d_in[1];
    const float* bt = (const float*)d_in[2];
    const float* Wp = (const float*)d_in[3];
    const float* bp = (const float*)d_in[4];
    const float* Wk = (const float*)d_in[5];
    const float* bk = (const float*)d_in[6];
    float* out = (float*)d_out;

    bf16 *xhi,*xlo,*WtThi,*WtTlo,*WpThi,*WpTlo,*Qhi,*Qlo,*Khi,*Klo;
    fp16 *xThi,*xTlo,*WkThi,*WkTlo,*Phi,*Yh;
    float *S, *Z;
    cudaGetSymbolAddress((void**)&xhi, g_xhi);   cudaGetSymbolAddress((void**)&xlo, g_xlo);
    cudaGetSymbolAddress((void**)&WtThi, g_WtThi); cudaGetSymbolAddress((void**)&WtTlo, g_WtTlo);
    cudaGetSymbolAddress((void**)&WpThi, g_WpThi); cudaGetSymbolAddress((void**)&WpTlo, g_WpTlo);
    cudaGetSymbolAddress((void**)&Qhi, g_Qhi);   cudaGetSymbolAddress((void**)&Qlo, g_Qlo);
    cudaGetSymbolAddress((void**)&Khi, g_Khi);   cudaGetSymbolAddress((void**)&Klo, g_Klo);
    cudaGetSymbolAddress((void**)&xThi, g_xThi); cudaGetSymbolAddress((void**)&xTlo, g_xTlo);
    cudaGetSymbolAddress((void**)&WkThi, g_WkThi); cudaGetSymbolAddress((void**)&WkTlo, g_WkTlo);
    cudaGetSymbolAddress((void**)&Phi, g_Phi);   cudaGetSymbolAddress((void**)&Yh, g_Yh);
    cudaGetSymbolAddress((void**)&S, g_S);       cudaGetSymbolAddress((void**)&Z, g_Z);

    cudaFuncSetAttribute(gemm_tc<0>, cudaFuncAttributeMaxDynamicSharedMemorySize, SMEM_BYTES);
    cudaFuncSetAttribute(gemm_tc<1>, cudaFuncAttributeMaxDynamicSharedMemorySize, SMEM_BYTES);

    // prep
    split_arr<<<512, 256>>>(x, xhi, xlo, (size_t)NTOK * CD);
    transpose_split_bf<<<dim3(CD/32, CD/32, 1), dim3(32, 8)>>>(Wt, WtThi, WtTlo, CD, CD);
    transpose_split_bf<<<dim3(CD/32, CD/32, 1), dim3(32, 8)>>>(Wp, WpThi, WpTlo, CD, CD);
    transpose_split_fp<<<dim3(CD/32, NTOK/32, 1), dim3(32, 8)>>>(x, xThi, xTlo, NTOK, CD);
    transpose_split_fp<<<dim3(CD/32, CD/32, NH), dim3(32, 8)>>>(Wk, WkThi, WkTlo, CD, CD);

    const int mt = NTOK / BM;            // 64
    // Q/K projections (bf16x3, split bf16 out)
    gemm_tc<0><<<mt * (CD/BN), 256, SMEM_BYTES>>>(
        (const uint16_t*)xhi, (const uint16_t*)xlo,
        (const uint16_t*)WtThi, (const uint16_t*)WtTlo,
        CD, CD, Qhi, Qlo, bt, 2, 0, 0, 0);
    gemm_tc<0><<<mt * (CD/BN), 256, SMEM_BYTES>>>(
        (const uint16_t*)xhi, (const uint16_t*)xlo,
        (const uint16_t*)WpThi, (const uint16_t*)WpTlo,
        CD, CD, Khi, Klo, bp, 2, 0, 0, 0);
    // sim (bf16x3, fp32 out)
    gemm_tc<0><<<mt * (NTOK/BN), 256, SMEM_BYTES>>>(
        (const uint16_t*)Qhi, (const uint16_t*)Qlo,
        (const uint16_t*)Khi, (const uint16_t*)Klo,
        CD, NTOK, S, nullptr, nullptr, 0, 0, 0, 0);
    // softmax -> fp16 P
    softmax_fp16<<<NTOK, 256>>>(S, Phi);
    // Y = P @ x (fp16x2 single-A, fp16 out)
    gemm_tc<1><<<mt * (CD/BN), 256, SMEM_BYTES>>>(
        (const uint16_t*)Phi, nullptr,
        (const uint16_t*)xThi, (const uint16_t*)xTlo,
        NTOK, CD, Yh, nullptr, nullptr, 4, 0, 0, 0);
    // Z[h] = Y @ Wk[h]^T + bk[h] (fp16x2 single-A, fp32 out)
    gemm_tc<1><<<dim3(mt * (CD/BN), 1, NH), 256, SMEM_BYTES>>>(
        (const uint16_t*)Yh, nullptr,
        (const uint16_t*)WkThi, (const uint16_t*)WkTlo,
        CD, CD, Z, nullptr, bk, 3,
        (size_t)CD * CD, (size_t)CD, (size_t)NTOK * CD);
    // out = mean_h relu(Z)
    reduce_heads<<<512, 256>>>(Z, out);
}

// round 7
// speedup vs baseline: 3.5206x; 1.0982x over previous
#include <cuda_runtime.h>
#include <cuda_bf16.h>
#include <cuda_fp16.h>
#include <cstdint>
#include <cstddef>

#define NTOK 8192
#define CD   512
#define NH   8

#define BM 128
#define BN 128
#define BK 32                      // 16-bit elements per chunk
#define KPW 20                     // padded row stride in words (80 B)
#define STAGES 2
#define MAT_WORDS (128 * KPW)          // 2560
#define STAGE_WORDS (4 * MAT_WORDS)    // 10240
#define SMEM_BYTES (STAGES * STAGE_WORDS * 4)   // 81920

typedef __nv_bfloat16 bf16;
typedef __half fp16;

// ---------------- scratch ----------------------------------------------------
__device__ bf16 g_xhi[NTOK*CD],  g_xlo[NTOK*CD];
__device__ bf16 g_WtThi[CD*CD],  g_WtTlo[CD*CD];
__device__ bf16 g_WpThi[CD*CD],  g_WpTlo[CD*CD];
__device__ bf16 g_Qhi[NTOK*CD],  g_Qlo[NTOK*CD];
__device__ bf16 g_Khi[NTOK*CD],  g_Klo[NTOK*CD];
__device__ fp16 g_xThi[CD*NTOK], g_xTlo[CD*NTOK];
__device__ fp16 g_WkThi[NH*CD*CD], g_WkTlo[NH*CD*CD];
__device__ fp16 g_Phi[(size_t)NTOK*NTOK];
__device__ fp16 g_Yh[NTOK*CD];
__device__ float g_S[(size_t)NTOK*NTOK];
__device__ float g_Z[(size_t)NH*NTOK*CD];

// ---------------- helpers ----------------------------------------------------
__device__ __forceinline__ uint32_t smem_u32(const void* p) {
    uint32_t a;
    asm("{ .reg .u64 t; cvta.to.shared.u64 t, %1; cvt.u32.u64 %0, t; }" : "=r"(a) : "l"(p));
    return a;
}
__device__ __forceinline__ void cp16(uint32_t d, const void* s) {
    asm volatile("cp.async.cg.shared.global [%0], [%1], 16;" :: "r"(d), "l"(s));
}
__device__ __forceinline__ void cp_commit() { asm volatile("cp.async.commit_group;"); }
__device__ __forceinline__ void cp_wait1()  { asm volatile("cp.async.wait_group 1;"); }

__device__ __forceinline__ void ldsm4(uint32_t& r0, uint32_t& r1, uint32_t& r2, uint32_t& r3,
                                      uint32_t addr) {
    asm volatile("ldmatrix.sync.aligned.m8n8.x4.shared.b16 {%0,%1,%2,%3}, [%4];"
                 : "=r"(r0), "=r"(r1), "=r"(r2), "=r"(r3) : "r"(addr));
}
__device__ __forceinline__ void mma_bf(float& c0, float& c1, float& c2, float& c3,
                                       uint32_t a0, uint32_t a1, uint32_t a2, uint32_t a3,
                                       uint32_t b0, uint32_t b1) {
    asm volatile(
        "mma.sync.aligned.m16n8k16.row.col.f32.bf16.bf16.f32 "
        "{%0,%1,%2,%3}, {%4,%5,%6,%7}, {%8,%9}, {%0,%1,%2,%3};"
        : "+f"(c0), "+f"(c1), "+f"(c2), "+f"(c3)
        : "r"(a0), "r"(a1), "r"(a2), "r"(a3), "r"(b0), "r"(b1));
}
__device__ __forceinline__ void mma_fp(float& c0, float& c1, float& c2, float& c3,
                                       uint32_t a0, uint32_t a1, uint32_t a2, uint32_t a3,
                                       uint32_t b0, uint32_t b1) {
    asm volatile(
        "mma.sync.aligned.m16n8k16.row.col.f32.f16.f16.f32 "
        "{%0,%1,%2,%3}, {%4,%5,%6,%7}, {%8,%9}, {%0,%1,%2,%3};"
        : "+f"(c0), "+f"(c1), "+f"(c2), "+f"(c3)
        : "r"(a0), "r"(a1), "r"(a2), "r"(a3), "r"(b0), "r"(b1));
}

// ---------------- tensor GEMM: C[8192, N] = A @ B^T -------------------------
// V=0: bf16x3 (A hi/lo in mats 0/1, B hi/lo in mats 2/3)
// V=1: fp16x2 single-A (A in mat 0, B hi/lo in mats 2/3)
// mode 0: fp32->C0   2: +bias, split bf16->C0/C1   3: +bias, fp32->C0   4: fp16->C0
template<int V>
__global__ __launch_bounds__(256, 2)
void gemm_tc(const uint16_t* __restrict__ Ahi, const uint16_t* __restrict__ Alo,
             const uint16_t* __restrict__ Bhi, const uint16_t* __restrict__ Blo,
             int K, int N, void* __restrict__ C0v, void* __restrict__ C1v,
             const float* __restrict__ bias, int mode,
             size_t strB, size_t strBias, size_t strC)
{
    extern __shared__ float sm[];
    const int tid  = threadIdx.x;
    const int wid  = tid >> 5, lane = tid & 31;
    const int gid  = lane >> 2, tig = lane & 3;
    const int wm   = wid & 3, wn = wid >> 2;

    const int z = blockIdx.z;
    Bhi += (size_t)z * strB;  Blo += (size_t)z * strB;
    if (bias) bias += (size_t)z * strBias;
    const size_t zC = (size_t)z * strC;

    const int mt_n = NTOK / BM, nt_n = N / BN;
    int tile = blockIdx.x;
    int npg  = 8 * nt_n;
    int grp  = tile / npg;
    int fm   = grp * 8;
    int gsz  = min(mt_n - fm, 8);
    int m_t  = fm + (tile % npg) % gsz;
    int n_t  = (tile % npg) / gsz;
    const int row0 = m_t * BM, col0 = n_t * BN;

    const uint32_t smb = smem_u32(sm);
    const int NC = K / BK;

    // per-lane ldmatrix address components (byte offsets within a matrix)
    const uint32_t laneA_off = (uint32_t)((wm * 32 + (lane & 15)) * KPW) * 4u
                             + ((lane >> 4) ? 16u : 0u);
    const uint32_t laneB_off = (uint32_t)((wn * 64 + (lane & 7) + ((lane & 16) ? 8 : 0)) * KPW) * 4u
                             + (((lane >> 3) & 1) ? 16u : 0u);

    auto load_chunk = [&](int c, int s) {
        const int k0 = c * BK;
        const int NIT = (V == 0) ? 8 : 6;
#pragma unroll
        for (int i = 0; i < NIT; ++i) {
            int id  = i * 256 + tid;
            int m3  = id >> 9;
            int mat = (V == 0) ? m3 : (m3 == 0 ? 0 : m3 + 1);
            const uint16_t* src = (mat == 0) ? Ahi : (mat == 1) ? Alo : (mat == 2) ? Bhi : Blo;
            int base = (mat <= 1) ? row0 : col0;
            int r   = (id >> 2) & 127;
            int c4  = id & 3;
            uint32_t dst = smb + (uint32_t)(s * STAGE_WORDS + mat * MAT_WORDS + r * KPW) * 4u
                         + (uint32_t)c4 * 16u;
            cp16(dst, src + (size_t)(base + r) * K + k0 + c4 * 8);
        }
    };

    float acc[2][8][4];
#pragma unroll
    for (int mt = 0; mt < 2; ++mt)
#pragma unroll
        for (int nt = 0; nt < 8; ++nt)
#pragma unroll
            for (int q = 0; q < 4; ++q) acc[mt][nt][q] = 0.f;

    load_chunk(0, 0); cp_commit();
    if (NC > 1) load_chunk(1, 1);
    cp_commit();

#pragma unroll 1
    for (int c = 0; c < NC; ++c) {
        const int s = c & 1;
        cp_wait1();
        __syncthreads();

        const uint32_t stage = smb + (uint32_t)(s * STAGE_WORDS) * 4u;
        const uint32_t aAh = stage + laneA_off;
        const uint32_t aAl = aAh + MAT_WORDS * 4u;
        const uint32_t aBh = stage + 2u * MAT_WORDS * 4u + laneB_off;
        const uint32_t aBl = aBh + MAT_WORDS * 4u;

#pragma unroll
        for (int ks = 0; ks < 2; ++ks) {
            const uint32_t ko = (uint32_t)ks * 32u;
            uint32_t ah[2][4], al[2][4];
#pragma unroll
            for (int mt = 0; mt < 2; ++mt) {
                ldsm4(ah[mt][0], ah[mt][1], ah[mt][2], ah[mt][3],
                      aAh + (uint32_t)(mt * 16 * KPW) * 4u + ko);
                if (V == 0)
                    ldsm4(al[mt][0], al[mt][1], al[mt][2], al[mt][3],
                          aAl + (uint32_t)(mt * 16 * KPW) * 4u + ko);
            }
#pragma unroll
            for (int p = 0; p < 4; ++p) {
                uint32_t bh0, bh1, bh2, bh3, bl0, bl1, bl2, bl3;
                ldsm4(bh0, bh1, bh2, bh3, aBh + (uint32_t)(p * 16 * KPW) * 4u + ko);
                ldsm4(bl0, bl1, bl2, bl3, aBl + (uint32_t)(p * 16 * KPW) * 4u + ko);
#pragma unroll
                for (int mt = 0; mt < 2; ++mt) {
                    float* ae = acc[mt][2 * p];
                    float* ao = acc[mt][2 * p + 1];
                    if (V == 0) {
                        mma_bf(ae[0], ae[1], ae[2], ae[3],
                               ah[mt][0], ah[mt][1], ah[mt][2], ah[mt][3], bh0, bh1);
                        mma_bf(ao[0], ao[1], ao[2], ao[3],
                               ah[mt][0], ah[mt][1], ah[mt][2], ah[mt][3], bh2, bh3);
                        mma_bf(ae[0], ae[1], ae[2], ae[3],
                               ah[mt][0], ah[mt][1], ah[mt][2], ah[mt][3], bl0, bl1);
                        mma_bf(ao[0], ao[1], ao[2], ao[3],
                               ah[mt][0], ah[mt][1], ah[mt][2], ah[mt][3], bl2, bl3);
                        mma_bf(ae[0], ae[1], ae[2], ae[3],
                               al[mt][0], al[mt][1], al[mt][2], al[mt][3], bh0, bh1);
                        mma_bf(ao[0], ao[1], ao[2], ao[3],
                               al[mt][0], al[mt][1], al[mt][2], al[mt][3], bh2, bh3);
                    } else {
                        mma_fp(ae[0], ae[1], ae[2], ae[3],
                               ah[mt][0], ah[mt][1], ah[mt][2], ah[mt][3], bh0, bh1);
                        mma_fp(ao[0], ao[1], ao[2], ao[3],
                               ah[mt][0], ah[mt][1], ah[mt][2], ah[mt][3], bh2, bh3);
                        mma_fp(ae[0], ae[1], ae[2], ae[3],
                               ah[mt][0], ah[mt][1], ah[mt][2], ah[mt][3], bl0, bl1);
                        mma_fp(ao[0], ao[1], ao[2], ao[3],
                               ah[mt][0], ah[mt][1], ah[mt][2], ah[mt][3], bl2, bl3);
                    }
                }
            }
        }
        __syncthreads();
        if (c + 2 < NC) load_chunk(c + 2, s);
        cp_commit();
    }

    // ---- epilogue ----
#pragma unroll
    for (int mt = 0; mt < 2; ++mt) {
#pragma unroll
        for (int nt = 0; nt < 8; ++nt) {
            int row = row0 + wm * 32 + mt * 16 + gid;
            int col = col0 + wn * 64 + nt * 8 + tig * 2;
            float v0 = acc[mt][nt][0], v1 = acc[mt][nt][1];
            float v2 = acc[mt][nt][2], v3 = acc[mt][nt][3];
            if (mode == 2 || mode == 3) {
                float b0 = bias[col], b1 = bias[col + 1];
                v0 += b0; v1 += b1; v2 += b0; v3 += b1;
            }
            size_t ad0 = (size_t)row * N + col;
            size_t ad1 = (size_t)(row + 8) * N + col;
            if (mode == 2) {
                bf16* o0 = (bf16*)C0v + zC;
                bf16* o1 = (bf16*)C1v + zC;
                bf16 h0 = __float2bfloat16(v0), h1 = __float2bfloat16(v1);
                bf16 h2 = __float2bfloat16(v2), h3 = __float2bfloat16(v3);
                __nv_bfloat162 hh0 = { h0, h1 }, hh1 = { h2, h3 };
                __nv_bfloat162 ll0 = { __float2bfloat16(v0 - __bfloat162float(h0)),
                                       __float2bfloat16(v1 - __bfloat162float(h1)) };
                __nv_bfloat162 ll1 = { __float2bfloat16(v2 - __bfloat162float(h2)),
                                       __float2bfloat16(v3 - __bfloat162float(h3)) };
                *(__nv_bfloat162*)(o0 + ad0) = hh0;  *(__nv_bfloat162*)(o0 + ad1) = hh1;
                *(__nv_bfloat162*)(o1 + ad0) = ll0;  *(__nv_bfloat162*)(o1 + ad1) = ll1;
            } else if (mode == 4) {
                fp16* o = (fp16*)C0v + zC;
                __half2 q0 = { __float2half(v0), __float2half(v1) };
                __half2 q1 = { __float2half(v2), __float2half(v3) };
                *(__half2*)(o + ad0) = q0;  *(__half2*)(o + ad1) = q1;
            } else {
                float* o = (float*)C0v + zC;
                float2 q0 = { v0, v1 }, q1 = { v2, v3 };
                *(float2*)(o + ad0) = q0;  *(float2*)(o + ad1) = q1;
            }
        }
    }
}

// ---------------- prep / softmax / reduce -----------------------------------
__global__ void split_arr(const float* __restrict__ s, bf16* __restrict__ hi,
                          bf16* __restrict__ lo, size_t n)
{
    for (size_t i = (size_t)blockIdx.x * blockDim.x + threadIdx.x; i < n;
         i += (size_t)gridDim.x * blockDim.x) {
        float v = s[i];
        bf16 h = __float2bfloat16(v);
        hi[i] = h;
        lo[i] = __float2bfloat16(v - __bfloat162float(h));
    }
}
__global__ void transpose_split_bf(const float* __restrict__ src, bf16* __restrict__ dhi,
                                   bf16* __restrict__ dlo, int R, int C)
{
    __shared__ float t[32][33];
    const size_t bo = (size_t)blockIdx.z * R * C;
    const float* s = src + bo;
    bf16* oh = dhi + bo; bf16* ol = dlo + bo;
    int c0 = blockIdx.x * 32, r0 = blockIdx.y * 32;
    int tx = threadIdx.x, ty = threadIdx.y;
#pragma unroll
    for (int i = 0; i < 4; ++i)
        t[ty + i*8][tx] = s[(size_t)(r0 + ty + i*8) * C + c0 + tx];
    __syncthreads();
#pragma unroll
    for (int i = 0; i < 4; ++i) {
        float v = t[tx][ty + i*8];
        bf16 h = __float2bfloat16(v);
        size_t ad = (size_t)(c0 + ty + i*8) * R + r0 + tx;
        oh[ad] = h;
        ol[ad] = __float2bfloat16(v - __bfloat162float(h));
    }
}
__global__ void transpose_split_fp(const float* __restrict__ src, fp16* __restrict__ dhi,
                                   fp16* __restrict__ dlo, int R, int C)
{
    __shared__ float t[32][33];
    const size_t bo = (size_t)blockIdx.z * R * C;
    const float* s = src + bo;
    fp16* oh = dhi + bo; fp16* ol = dlo + bo;
    int c0 = blockIdx.x * 32, r0 = blockIdx.y * 32;
    int tx = threadIdx.x, ty = threadIdx.y;
#pragma unroll
    for (int i = 0; i < 4; ++i)
        t[ty + i*8][tx] = s[(size_t)(r0 + ty + i*8) * C + c0 + tx];
    __syncthreads();
#pragma unroll
    for (int i = 0; i < 4; ++i) {
        float v = t[tx][ty + i*8];
        fp16 h = __float2half(v);
        size_t ad = (size_t)(c0 + ty + i*8) * R + r0 + tx;
        oh[ad] = h;
        ol[ad] = __float2half(v - __half2float(h));
    }
}
__device__ __forceinline__ float wmax(float v) {
#pragma unroll
    for (int o = 16; o > 0; o >>= 1) v = fmaxf(v, __shfl_xor_sync(0xffffffffu, v, o));
    return v;
}
__device__ __forceinline__ float wsum(float v) {
#pragma unroll
    for (int o = 16; o > 0; o >>= 1) v += __shfl_xor_sync(0xffffffffu, v, o);
    return v;
}
__global__ __launch_bounds__(256, 4)
void softmax_fp16(const float* __restrict__ S, fp16* __restrict__ Phi)
{
    const float* r = S + (size_t)blockIdx.x * NTOK;
    fp16* ph = Phi + (size_t)blockIdx.x * NTOK;
    const int tid = threadIdx.x;
    __shared__ float red[8];
    float v[32];
    float m = -3.4e38f;
#pragma unroll
    for (int i = 0; i < 32; ++i) { v[i] = r[i*256 + tid]; m = fmaxf(m, v[i]); }
    m = wmax(m);
    if ((tid & 31) == 0) red[tid >> 5] = m;
    __syncthreads();
    { float t = red[tid & 7];
      t = fmaxf(t, __shfl_xor_sync(0xffffffffu, t, 1));
      t = fmaxf(t, __shfl_xor_sync(0xffffffffu, t, 2));
      t = fmaxf(t, __shfl_xor_sync(0xffffffffu, t, 4)); m = t; }
    float s = 0.f;
#pragma unroll
    for (int i = 0; i < 32; ++i) { v[i] = __expf(v[i] - m); s += v[i]; }
    s = wsum(s);
    __syncthreads();
    if ((tid & 31) == 0) red[tid >> 5] = s;
    __syncthreads();
    { float t = red[tid & 7];
      t += __shfl_xor_sync(0xffffffffu, t, 1);
      t += __shfl_xor_sync(0xffffffffu, t, 2);
      t += __shfl_xor_sync(0xffffffffu, t, 4); s = t; }
    const float inv = 1.f / s;
#pragma unroll
    for (int i = 0; i < 32; ++i)
        ph[i*256 + tid] = __float2half(v[i] * inv);
}
__global__ void reduce_heads(const float* __restrict__ Z, float* __restrict__ out)
{
    const size_t n = (size_t)NTOK * CD / 4;
    const size_t str = (size_t)NTOK * CD / 4;
    const float4* z = (const float4*)Z;
    for (size_t i = (size_t)blockIdx.x * blockDim.x + threadIdx.x; i < n;
         i += (size_t)gridDim.x * blockDim.x) {
        float4 a = { 0.f, 0.f, 0.f, 0.f };
#pragma unroll
        for (int h = 0; h < NH; ++h) {
            float4 v = z[h * str + i];
            a.x += fmaxf(v.x, 0.f); a.y += fmaxf(v.y, 0.f);
            a.z += fmaxf(v.z, 0.f); a.w += fmaxf(v.w, 0.f);
        }
        a.x *= 0.125f; a.y *= 0.125f; a.z *= 0.125f; a.w *= 0.125f;
        ((float4*)out)[i] = a;
    }
}

// ---------------- host -------------------------------------------------------
extern "C" void kernel_launch(void* const* d_in, const int* in_sizes, int n_in,
                              void* d_out, int out_size)
{
    (void)in_sizes; (void)n_in; (void)out_size;
    const float* x  = (const float*)d_in[0];
    const float* Wt = (const float*)d_in[1];
    const float* bt = (const float*)d_in[2];
    const float* Wp = (const float*)d_in[3];
    const float* bp = (const float*)d_in[4];
    const float* Wk = (const float*)d_in[5];
    const float* bk = (const float*)d_in[6];
    float* out = (float*)d_out;

    bf16 *xhi,*xlo,*WtThi,*WtTlo,*WpThi,*WpTlo,*Qhi,*Qlo,*Khi,*Klo;
    fp16 *xThi,*xTlo,*WkThi,*WkTlo,*Phi,*Yh;
    float *S, *Z;
    cudaGetSymbolAddress((void**)&xhi, g_xhi);   cudaGetSymbolAddress((void**)&xlo, g_xlo);
    cudaGetSymbolAddress((void**)&WtThi, g_WtThi); cudaGetSymbolAddress((void**)&WtTlo, g_WtTlo);
    cudaGetSymbolAddress((void**)&WpThi, g_WpThi); cudaGetSymbolAddress((void**)&WpTlo, g_WpTlo);
    cudaGetSymbolAddress((void**)&Qhi, g_Qhi);   cudaGetSymbolAddress((void**)&Qlo, g_Qlo);
    cudaGetSymbolAddress((void**)&Khi, g_Khi);   cudaGetSymbolAddress((void**)&Klo, g_Klo);
    cudaGetSymbolAddress((void**)&xThi, g_xThi); cudaGetSymbolAddress((void**)&xTlo, g_xTlo);
    cudaGetSymbolAddress((void**)&WkThi, g_WkThi); cudaGetSymbolAddress((void**)&WkTlo, g_WkTlo);
    cudaGetSymbolAddress((void**)&Phi, g_Phi);   cudaGetSymbolAddress((void**)&Yh, g_Yh);
    cudaGetSymbolAddress((void**)&S, g_S);       cudaGetSymbolAddress((void**)&Z, g_Z);

    cudaFuncSetAttribute(gemm_tc<0>, cudaFuncAttributeMaxDynamicSharedMemorySize, SMEM_BYTES);
    cudaFuncSetAttribute(gemm_tc<1>, cudaFuncAttributeMaxDynamicSharedMemorySize, SMEM_BYTES);

    // prep
    split_arr<<<512, 256>>>(x, xhi, xlo, (size_t)NTOK * CD);
    transpose_split_bf<<<dim3(CD/32, CD/32, 1), dim3(32, 8)>>>(Wt, WtThi, WtTlo, CD, CD);
    transpose_split_bf<<<dim3(CD/32, CD/32, 1), dim3(32, 8)>>>(Wp, WpThi, WpTlo, CD, CD);
    transpose_split_fp<<<dim3(CD/32, NTOK/32, 1), dim3(32, 8)>>>(x, xThi, xTlo, NTOK, CD);
    transpose_split_fp<<<dim3(CD/32, CD/32, NH), dim3(32, 8)>>>(Wk, WkThi, WkTlo, CD, CD);

    const int mt = NTOK / BM;            // 64
    gemm_tc<0><<<mt * (CD/BN), 256, SMEM_BYTES>>>(
        (const uint16_t*)xhi, (const uint16_t*)xlo,
        (const uint16_t*)WtThi, (const uint16_t*)WtTlo,
        CD, CD, Qhi, Qlo, bt, 2, 0, 0, 0);
    gemm_tc<0><<<mt * (CD/BN), 256, SMEM_BYTES>>>(
        (const uint16_t*)xhi, (const uint16_t*)xlo,
        (const uint16_t*)WpThi, (const uint16_t*)WpTlo,
        CD, CD, Khi, Klo, bp, 2, 0, 0, 0);
    gemm_tc<0><<<mt * (NTOK/BN), 256, SMEM_BYTES>>>(
        (const uint16_t*)Qhi, (const uint16_t*)Qlo,
        (const uint16_t*)Khi, (const uint16_t*)Klo,
        CD, NTOK, S, nullptr, nullptr, 0, 0, 0, 0);
    softmax_fp16<<<NTOK, 256>>>(S, Phi);
    gemm_tc<1><<<mt * (CD/BN), 256, SMEM_BYTES>>>(
        (const uint16_t*)Phi, nullptr,
        (const uint16_t*)xThi, (const uint16_t*)xTlo,
        NTOK, CD, Yh, nullptr, nullptr, 4, 0, 0, 0);
    gemm_tc<1><<<dim3(mt * (CD/BN), 1, NH), 256, SMEM_BYTES>>>(
        (const uint16_t*)Yh, nullptr,
        (const uint16_t*)WkThi, (const uint16_t*)WkTlo,
        CD, CD, Z, nullptr, bk, 3,
        (size_t)CD * CD, (size_t)CD, (size_t)NTOK * CD);
    reduce_heads<<<512, 256>>>(Z, out);
}